// round 12
// baseline (speedup 1.0000x reference)
#include <cuda_runtime.h>
#include <cuda_bf16.h>
#include <math.h>
#include <stdint.h>

#define DMODEL 1024
#define SEQT   2048
#define BATCH  2
#define MROWS  4096   // BATCH * SEQT
#define NHEAD  16
#define HDIM   64
#define DM3    (3 * DMODEL)

// ---------------- scratch (static device allocations) ----------------
__device__ float g_x2 [MROWS * DMODEL];
__device__ __nv_bfloat16 g_lnh [MROWS * DMODEL], g_lnl [MROWS * DMODEL];
__device__ __nv_bfloat16 g_qkvh[MROWS * DM3],    g_qkvl[MROWS * DM3];
__device__ __nv_bfloat16 g_ctxh[MROWS * DMODEL], g_ctxl[MROWS * DMODEL];
__device__ __nv_bfloat16 g_ffh [MROWS * 2 * DMODEL], g_ffl [MROWS * 2 * DMODEL];

__device__ __nv_bfloat16 g_Bqkv_h[DM3 * DMODEL], g_Bqkv_l[DM3 * DMODEL];
__device__ __nv_bfloat16 g_Bo_h[DMODEL * DMODEL], g_Bo_l[DMODEL * DMODEL];
__device__ __nv_bfloat16 g_B1_h[2 * DMODEL * DMODEL], g_B1_l[2 * DMODEL * DMODEL];
__device__ __nv_bfloat16 g_B2_h[2 * DMODEL * DMODEL], g_B2_l[2 * DMODEL * DMODEL];

// ---------------- helpers --------------------------------------------
__device__ __forceinline__ uint32_t smem_u32(const void* p) {
    uint32_t a;
    asm("{ .reg .u64 t; cvta.to.shared.u64 t, %1; cvt.u32.u64 %0, t; }"
        : "=r"(a) : "l"(p));
    return a;
}
__device__ __forceinline__ float gelu_exact(float x) {
    return 0.5f * x * (1.0f + erff(x * 0.70710678118654752f));
}
__device__ __forceinline__ void split2(float x, float y, uint32_t& h, uint32_t& l) {
    __nv_bfloat162 hh = __float22bfloat162_rn(make_float2(x, y));
    float2 f = __bfloat1622float2(hh);
    __nv_bfloat162 ll = __float22bfloat162_rn(make_float2(x - f.x, y - f.y));
    h = *(uint32_t*)&hh;
    l = *(uint32_t*)&ll;
}

#define LDM_X4(r0, r1, r2, r3, addr) \
    asm volatile("ldmatrix.sync.aligned.m8n8.x4.shared.b16 {%0,%1,%2,%3}, [%4];" \
        : "=r"(r0), "=r"(r1), "=r"(r2), "=r"(r3) : "r"(addr))
#define LDM_X4T(r0, r1, r2, r3, addr) \
    asm volatile("ldmatrix.sync.aligned.m8n8.x4.trans.shared.b16 {%0,%1,%2,%3}, [%4];" \
        : "=r"(r0), "=r"(r1), "=r"(r2), "=r"(r3) : "r"(addr))

#define MMA16816(d, a, b0, b1) \
    asm volatile("mma.sync.aligned.m16n8k16.row.col.f32.bf16.bf16.f32 " \
        "{%0,%1,%2,%3}, {%4,%5,%6,%7}, {%8,%9}, {%0,%1,%2,%3};" \
        : "+f"((d)[0]), "+f"((d)[1]), "+f"((d)[2]), "+f"((d)[3]) \
        : "r"((a)[0]), "r"((a)[1]), "r"((a)[2]), "r"((a)[3]), \
          "r"(b0), "r"(b1))

#define CP16(dst, src) \
    asm volatile("cp.async.cg.shared.global [%0], [%1], 16;" \
        :: "r"(dst), "l"(src))
#define CP_COMMIT() asm volatile("cp.async.commit_group;")
#define CP_WAIT2()  asm volatile("cp.async.wait_group 2;")
#define CP_WAIT1()  asm volatile("cp.async.wait_group 1;")
#define CP_WAIT0()  asm volatile("cp.async.wait_group 0;")

// 64B-row tile swizzle for GEMM smem.
#define SWZ64(off) ((off) ^ ((((off) >> 7) & 3u) << 4))

// ---------------- weight prep ----------------------------------------
__global__ void __launch_bounds__(256) wsplit_all_kernel(
    const float* __restrict__ Wq, const float* __restrict__ Wk,
    const float* __restrict__ Wv,
    __nv_bfloat16* __restrict__ Bqkv_h, __nv_bfloat16* __restrict__ Bqkv_l,
    const float* __restrict__ Wo, __nv_bfloat16* __restrict__ Bo_h, __nv_bfloat16* __restrict__ Bo_l,
    const float* __restrict__ W1, __nv_bfloat16* __restrict__ B1_h, __nv_bfloat16* __restrict__ B1_l,
    const float* __restrict__ W2, __nv_bfloat16* __restrict__ B2_h, __nv_bfloat16* __restrict__ B2_l) {
    __shared__ float t[32][33];
    int bid = blockIdx.x;
    const float* W;
    __nv_bfloat16 *Th, *Tl;
    int K, N, k0, n0, nout;
    if (bid < 4096) {
        int w = bid >> 10, lb = bid & 1023;
        K = DMODEL; N = DMODEL;
        k0 = (lb & 31) * 32; n0 = (lb >> 5) * 32;
        if (w < 3) {
            W = (w == 0) ? Wq : (w == 1) ? Wk : Wv;
            Th = Bqkv_h; Tl = Bqkv_l;
            nout = n0 + w * DMODEL;
        } else {
            W = Wo; Th = Bo_h; Tl = Bo_l; nout = n0;
        }
    } else if (bid < 6144) {
        int lb = bid - 4096;
        K = DMODEL; N = 2 * DMODEL;
        k0 = (lb & 31) * 32; n0 = (lb >> 5) * 32;
        W = W1; Th = B1_h; Tl = B1_l; nout = n0;
    } else {
        int lb = bid - 6144;
        K = 2 * DMODEL; N = DMODEL;
        k0 = (lb & 63) * 32; n0 = (lb >> 6) * 32;
        W = W2; Th = B2_h; Tl = B2_l; nout = n0;
    }
    int tx = threadIdx.x & 31, ty = threadIdx.x >> 5;
    #pragma unroll
    for (int i = 0; i < 4; ++i)
        t[ty + i * 8][tx] = W[(size_t)(k0 + ty + i * 8) * N + n0 + tx];
    __syncthreads();
    #pragma unroll
    for (int i = 0; i < 4; ++i) {
        int n = nout + ty + i * 8, k = k0 + tx;
        float x = t[tx][ty + i * 8];
        __nv_bfloat16 h = __float2bfloat16_rn(x);
        float lo = x - __bfloat162float(h);
        Th[(size_t)n * K + k] = h;
        Tl[(size_t)n * K + k] = __float2bfloat16_rn(lo);
    }
}

// ---------------- LayerNorm -> bf16 hi/lo ----------------------------
__global__ void __launch_bounds__(256) ln_kernel(const float* __restrict__ x,
                                                 const float* __restrict__ g,
                                                 const float* __restrict__ b,
                                                 __nv_bfloat16* __restrict__ outh,
                                                 __nv_bfloat16* __restrict__ outl) {
    int row = blockIdx.x;
    int tid = threadIdx.x;
    const float4* xr = (const float4*)(x + (size_t)row * DMODEL);
    float4 v = xr[tid];
    float s  = v.x + v.y + v.z + v.w;
    float ss = v.x * v.x + v.y * v.y + v.z * v.z + v.w * v.w;
    #pragma unroll
    for (int o = 16; o > 0; o >>= 1) {
        s  += __shfl_xor_sync(0xffffffffu, s,  o);
        ss += __shfl_xor_sync(0xffffffffu, ss, o);
    }
    __shared__ float sh[16];
    int w = tid >> 5;
    if ((tid & 31) == 0) { sh[w] = s; sh[8 + w] = ss; }
    __syncthreads();
    if (tid < 32) {
        float a  = (tid < 8) ? sh[tid]     : 0.0f;
        float a2 = (tid < 8) ? sh[8 + tid] : 0.0f;
        #pragma unroll
        for (int o = 4; o > 0; o >>= 1) {
            a  += __shfl_xor_sync(0xffffffffu, a,  o);
            a2 += __shfl_xor_sync(0xffffffffu, a2, o);
        }
        if (tid == 0) { sh[0] = a; sh[1] = a2; }
    }
    __syncthreads();
    float mean = sh[0] * (1.0f / DMODEL);
    float var  = sh[1] * (1.0f / DMODEL) - mean * mean;
    float rstd = rsqrtf(var + 1e-5f);
    float4 gg = ((const float4*)g)[tid];
    float4 bb = ((const float4*)b)[tid];
    float o0 = (v.x - mean) * rstd * gg.x + bb.x;
    float o1 = (v.y - mean) * rstd * gg.y + bb.y;
    float o2 = (v.z - mean) * rstd * gg.z + bb.z;
    float o3 = (v.w - mean) * rstd * gg.w + bb.w;
    uint2 h, l;
    split2(o0, o1, h.x, l.x);
    split2(o2, o3, h.y, l.y);
    ((uint2*)(outh + (size_t)row * DMODEL))[tid] = h;
    ((uint2*)(outl + (size_t)row * DMODEL))[tid] = l;
}

// ---------------- HMMA GEMM (r11 proven): 256 thr, 3-stage swizzled --
#define HG_A_L   8192
#define HG_B     16384
#define HG_B_L   8192
#define HG_STAGE 32768
#define HG_SMEM_BYTES (3 * HG_STAGE)

template <int GELU, int HAS_BIAS, int HAS_RES, int OSPLIT>
__global__ void __launch_bounds__(256, 2) hgemm_kernel(
    const __nv_bfloat16* __restrict__ Ah, const __nv_bfloat16* __restrict__ Al,
    const __nv_bfloat16* __restrict__ Bh, const __nv_bfloat16* __restrict__ Bl,
    const float* __restrict__ bias, const float* __restrict__ res,
    float* __restrict__ C, __nv_bfloat16* __restrict__ Ch,
    __nv_bfloat16* __restrict__ Cl, int M, int N, int K) {
    extern __shared__ __align__(16) char smem[];
    uint32_t uS = smem_u32(smem);

    int tid = threadIdx.x;
    int lane = tid & 31, wid = tid >> 5;
    int wm = wid >> 2, wn = wid & 3;
    int bm = blockIdx.y * 128, bn = blockIdx.x * 128;

    float acc[4][4][4];
    #pragma unroll
    for (int i = 0; i < 4; ++i)
        #pragma unroll
        for (int j = 0; j < 4; ++j)
            #pragma unroll
            for (int k = 0; k < 4; ++k) acc[i][j][k] = 0.0f;

    int q = lane >> 3, rr = lane & 7;
    int a_row = wm * 64 + (q & 1) * 8 + rr;
    int a_cb  = 16 * (q >> 1);
    int b_row = wn * 32 + (q >> 1) * 8 + rr;
    int b_cb  = 16 * (q & 1);

    int lr = tid >> 2, lck = (tid & 3) << 4;
    const int NC = K >> 5;

    auto load_chunk = [&](int c, int s) {
        uint32_t sb = uS + (uint32_t)s * HG_STAGE;
        int kc = c << 5;
        #pragma unroll
        for (int i = 0; i < 2; ++i) {
            int r = lr + i * 64;
            uint32_t d = sb + SWZ64((uint32_t)(r * 64 + lck));
            CP16(d, Ah + (size_t)(bm + r) * K + kc + (lck >> 1));
            CP16(d + HG_A_L, Al + (size_t)(bm + r) * K + kc + (lck >> 1));
        }
        #pragma unroll
        for (int i = 0; i < 2; ++i) {
            int r = lr + i * 64;
            uint32_t d = sb + HG_B + SWZ64((uint32_t)(r * 64 + lck));
            CP16(d, Bh + (size_t)(bn + r) * K + kc + (lck >> 1));
            CP16(d + HG_B_L, Bl + (size_t)(bn + r) * K + kc + (lck >> 1));
        }
        CP_COMMIT();
    };

    load_chunk(0, 0);
    if (NC > 1) load_chunk(1, 1);

    for (int c = 0; c < NC; ++c) {
        if (c + 2 < NC) { load_chunk(c + 2, (c + 2) % 3); CP_WAIT2(); }
        else if (c + 1 < NC) { CP_WAIT1(); }
        else { CP_WAIT0(); }
        __syncthreads();

        uint32_t sb = uS + (uint32_t)(c % 3) * HG_STAGE;
        #pragma unroll
        for (int ks = 0; ks < 2; ++ks) {
            uint32_t ahf[4][4], alf[4][4];
            #pragma unroll
            for (int mi = 0; mi < 4; ++mi) {
                uint32_t off = sb + SWZ64(
                    (uint32_t)((a_row + mi * 16) * 64 + a_cb + ks * 32));
                LDM_X4(ahf[mi][0], ahf[mi][1], ahf[mi][2], ahf[mi][3], off);
                LDM_X4(alf[mi][0], alf[mi][1], alf[mi][2], alf[mi][3], off + HG_A_L);
            }
            #pragma unroll
            for (int j2 = 0; j2 < 2; ++j2) {
                uint32_t bhf[2][2], blf[2][2];
                uint32_t off = sb + HG_B + SWZ64(
                    (uint32_t)((b_row + j2 * 16) * 64 + b_cb + ks * 32));
                LDM_X4(bhf[0][0], bhf[0][1], bhf[1][0], bhf[1][1], off);
                LDM_X4(blf[0][0], blf[0][1], blf[1][0], blf[1][1], off + HG_B_L);
                #pragma unroll
                for (int mi = 0; mi < 4; ++mi)
                    #pragma unroll
                    for (int nj = 0; nj < 2; ++nj) {
                        int ni = j2 * 2 + nj;
                        MMA16816(acc[mi][ni], ahf[mi], bhf[nj][0], bhf[nj][1]);
                        MMA16816(acc[mi][ni], alf[mi], bhf[nj][0], bhf[nj][1]);
                        MMA16816(acc[mi][ni], ahf[mi], blf[nj][0], blf[nj][1]);
                    }
            }
        }
        __syncthreads();
    }

    int gid = lane >> 2, tig = lane & 3;
    #pragma unroll
    for (int mi = 0; mi < 4; ++mi) {
        #pragma unroll
        for (int ni = 0; ni < 4; ++ni) {
            int row0 = bm + wm * 64 + mi * 16 + gid;
            int col  = bn + wn * 32 + ni * 8 + tig * 2;
            float c0 = acc[mi][ni][0], c1 = acc[mi][ni][1];
            float c2 = acc[mi][ni][2], c3 = acc[mi][ni][3];
            if (HAS_BIAS) {
                float b0 = bias[col], b1v = bias[col + 1];
                c0 += b0; c1 += b1v; c2 += b0; c3 += b1v;
            }
            if (GELU) {
                c0 = gelu_exact(c0); c1 = gelu_exact(c1);
                c2 = gelu_exact(c2); c3 = gelu_exact(c3);
            }
            if (HAS_RES) {
                float2 r0 = *(const float2*)&res[(size_t)row0 * N + col];
                float2 r1 = *(const float2*)&res[(size_t)(row0 + 8) * N + col];
                c0 += r0.x; c1 += r0.y; c2 += r1.x; c3 += r1.y;
            }
            if (OSPLIT) {
                uint32_t h0, l0, h1, l1;
                split2(c0, c1, h0, l0);
                split2(c2, c3, h1, l1);
                *(uint32_t*)&Ch[(size_t)row0 * N + col] = h0;
                *(uint32_t*)&Cl[(size_t)row0 * N + col] = l0;
                *(uint32_t*)&Ch[(size_t)(row0 + 8) * N + col] = h1;
                *(uint32_t*)&Cl[(size_t)(row0 + 8) * N + col] = l1;
            } else {
                float2 o0; o0.x = c0; o0.y = c1;
                float2 o1; o1.x = c2; o1.y = c3;
                *(float2*)&C[(size_t)row0 * N + col] = o0;
                *(float2*)&C[(size_t)(row0 + 8) * N + col] = o1;
            }
        }
    }
}

// ---------------- Tensor-core flash attention: 256 thr, 128q x 64k ---
// 8 warps x 16 q-rows each (per-warp inner loop identical to proven r9).
// 16 warps/SM at 2 CTAs/SM; K/V traffic halves per unit compute.
#define AT_PAD   72
#define AT_QL    18432
#define AT_Q     36864
#define AT_TILE  9216
#define AT_STAGE 36864
#define AT_SMEM  (AT_Q + 2 * AT_STAGE)  // 110592

__global__ void __launch_bounds__(256) attn_kernel(
    const __nv_bfloat16* __restrict__ QKVh, const __nv_bfloat16* __restrict__ QKVl,
    __nv_bfloat16* __restrict__ Oh, __nv_bfloat16* __restrict__ Ol) {
    extern __shared__ __align__(16) char smem[];
    uint32_t uS = smem_u32(smem);

    int qt = 15 - (int)blockIdx.x;     // heavy-first
    int bh = blockIdx.y;
    int b = bh >> 4, h = bh & 15;
    int tid = threadIdx.x, lane = tid & 31, wid = tid >> 5;  // wid 0..7
    int gid = lane >> 2, tig = lane & 3;
    int q = lane >> 3, rr = lane & 7;

    size_t rowbase = (size_t)b * SEQT;

    auto ld_q = [&](const __nv_bfloat16* G, uint32_t dst) {
        #pragma unroll
        for (int i = 0; i < 4; ++i) {
            int idx = tid + i * 256;
            int r = idx >> 3, c8 = (idx & 7) << 3;
            CP16(dst + (uint32_t)(r * AT_PAD + c8) * 2,
                 G + (rowbase + qt * 128 + r) * (size_t)DM3 + h * HDIM + c8);
        }
    };
    auto ld_kv = [&](const __nv_bfloat16* G, uint32_t dst, int trow, int cbase) {
        #pragma unroll
        for (int i = 0; i < 2; ++i) {
            int idx = tid + i * 256;
            int r = idx >> 3, c8 = (idx & 7) << 3;
            CP16(dst + (uint32_t)(r * AT_PAD + c8) * 2,
                 G + (rowbase + trow + r) * (size_t)DM3 + cbase + h * HDIM + c8);
        }
    };

    ld_q(QKVh, uS);
    ld_q(QKVl, uS + AT_QL);
    ld_kv(QKVh, uS + AT_Q, 0, DMODEL);
    ld_kv(QKVl, uS + AT_Q + AT_TILE, 0, DMODEL);
    ld_kv(QKVh, uS + AT_Q + 2 * AT_TILE, 0, 2 * DMODEL);
    ld_kv(QKVl, uS + AT_Q + 3 * AT_TILE, 0, 2 * DMODEL);
    CP_COMMIT();

    float oacc[8][4];
    #pragma unroll
    for (int i = 0; i < 8; ++i)
        #pragma unroll
        for (int j = 0; j < 4; ++j) oacc[i][j] = 0.0f;
    float m0 = -1e30f, m1 = -1e30f, l0 = 0.0f, l1 = 0.0f;

    int a_row   = wid * 16 + (q & 1) * 8 + rr;
    int a_csel  = (q >> 1) * 8;
    int b_rsel  = (q >> 1) * 8 + rr;
    int b_csel  = (q & 1) * 8;
    int v_rsel  = (q & 1) * 8 + rr;
    int v_csel  = (q >> 1) * 8;

    int nkt = 2 * qt + 2;
    for (int kt = 0; kt < nkt; ++kt) {
        uint32_t st = uS + AT_Q + (uint32_t)(kt & 1) * AT_STAGE;
        if (kt + 1 < nkt) {
            uint32_t s2 = uS + AT_Q + (uint32_t)((kt + 1) & 1) * AT_STAGE;
            ld_kv(QKVh, s2, (kt + 1) * 64, DMODEL);
            ld_kv(QKVl, s2 + AT_TILE, (kt + 1) * 64, DMODEL);
            ld_kv(QKVh, s2 + 2 * AT_TILE, (kt + 1) * 64, 2 * DMODEL);
            ld_kv(QKVl, s2 + 3 * AT_TILE, (kt + 1) * 64, 2 * DMODEL);
            CP_COMMIT();
            CP_WAIT1();
        } else {
            CP_WAIT0();
        }
        __syncthreads();

        // ---- S = Q K^T (3-product split) ----
        float sc[8][4];
        #pragma unroll
        for (int i = 0; i < 8; ++i)
            #pragma unroll
            for (int j = 0; j < 4; ++j) sc[i][j] = 0.0f;

        #pragma unroll
        for (int ks = 0; ks < 4; ++ks) {
            uint32_t qhf[4], qlf[4];
            uint32_t aoff = (uint32_t)(a_row * AT_PAD + a_csel + ks * 16) * 2;
            LDM_X4(qhf[0], qhf[1], qhf[2], qhf[3], uS + aoff);
            LDM_X4(qlf[0], qlf[1], qlf[2], qlf[3], uS + AT_QL + aoff);
            #pragma unroll
            for (int j2 = 0; j2 < 4; ++j2) {
                uint32_t kh0, kh1, kh2, kh3, kl0, kl1, kl2, kl3;
                uint32_t boff = st +
                    (uint32_t)((j2 * 16 + b_rsel) * AT_PAD + b_csel + ks * 16) * 2;
                LDM_X4(kh0, kh1, kh2, kh3, boff);
                LDM_X4(kl0, kl1, kl2, kl3, boff + AT_TILE);
                MMA16816(sc[2 * j2],     qhf, kh0, kh1);
                MMA16816(sc[2 * j2],     qlf, kh0, kh1);
                MMA16816(sc[2 * j2],     qhf, kl0, kl1);
                MMA16816(sc[2 * j2 + 1], qhf, kh2, kh3);
                MMA16816(sc[2 * j2 + 1], qlf, kh2, kh3);
                MMA16816(sc[2 * j2 + 1], qhf, kl2, kl3);
            }
        }

        // scale + causal mask (global row/col compare, last two k-tiles)
        #pragma unroll
        for (int ni = 0; ni < 8; ++ni) {
            sc[ni][0] *= 0.125f; sc[ni][1] *= 0.125f;
            sc[ni][2] *= 0.125f; sc[ni][3] *= 0.125f;
        }
        if (kt >= 2 * qt) {
            int r0 = qt * 128 + wid * 16 + gid, r1 = r0 + 8;
            #pragma unroll
            for (int ni = 0; ni < 8; ++ni) {
                int c0 = kt * 64 + ni * 8 + tig * 2, c1 = c0 + 1;
                if (c0 > r0) sc[ni][0] = -1e30f;
                if (c1 > r0) sc[ni][1] = -1e30f;
                if (c0 > r1) sc[ni][2] = -1e30f;
                if (c1 > r1) sc[ni][3] = -1e30f;
            }
        }

        // ---- online softmax in registers ----
        float t0 = -1e30f, t1 = -1e30f;
        #pragma unroll
        for (int ni = 0; ni < 8; ++ni) {
            t0 = fmaxf(t0, fmaxf(sc[ni][0], sc[ni][1]));
            t1 = fmaxf(t1, fmaxf(sc[ni][2], sc[ni][3]));
        }
        t0 = fmaxf(t0, __shfl_xor_sync(0xffffffffu, t0, 1));
        t0 = fmaxf(t0, __shfl_xor_sync(0xffffffffu, t0, 2));
        t1 = fmaxf(t1, __shfl_xor_sync(0xffffffffu, t1, 1));
        t1 = fmaxf(t1, __shfl_xor_sync(0xffffffffu, t1, 2));
        float mn0 = fmaxf(m0, t0), mn1 = fmaxf(m1, t1);
        float al0 = __expf(m0 - mn0), al1 = __expf(m1 - mn1);
        m0 = mn0; m1 = mn1;

        float sum0 = 0.0f, sum1 = 0.0f;
        uint32_t pah[4][4], pal[4][4];
        #pragma unroll
        for (int kp = 0; kp < 4; ++kp) {
            float p00 = __expf(sc[2 * kp][0] - mn0);
            float p01 = __expf(sc[2 * kp][1] - mn0);
            float p02 = __expf(sc[2 * kp][2] - mn1);
            float p03 = __expf(sc[2 * kp][3] - mn1);
            float p10 = __expf(sc[2 * kp + 1][0] - mn0);
            float p11 = __expf(sc[2 * kp + 1][1] - mn0);
            float p12 = __expf(sc[2 * kp + 1][2] - mn1);
            float p13 = __expf(sc[2 * kp + 1][3] - mn1);
            sum0 += p00 + p01 + p10 + p11;
            sum1 += p02 + p03 + p12 + p13;
            split2(p00, p01, pah[kp][0], pal[kp][0]);
            split2(p02, p03, pah[kp][1], pal[kp][1]);
            split2(p10, p11, pah[kp][2], pal[kp][2]);
            split2(p12, p13, pah[kp][3], pal[kp][3]);
        }
        sum0 += __shfl_xor_sync(0xffffffffu, sum0, 1);
        sum0 += __shfl_xor_sync(0xffffffffu, sum0, 2);
        sum1 += __shfl_xor_sync(0xffffffffu, sum1, 1);
        sum1 += __shfl_xor_sync(0xffffffffu, sum1, 2);
        l0 = l0 * al0 + sum0;
        l1 = l1 * al1 + sum1;
        #pragma unroll
        for (int ni = 0; ni < 8; ++ni) {
            oacc[ni][0] *= al0; oacc[ni][1] *= al0;
            oacc[ni][2] *= al1; oacc[ni][3] *= al1;
        }

        // ---- O += P V ----
        #pragma unroll
        for (int ks = 0; ks < 4; ++ks) {
            #pragma unroll
            for (int j2 = 0; j2 < 4; ++j2) {
                uint32_t vh0, vh1, vh2, vh3, vl0, vl1, vl2, vl3;
                uint32_t voff = st + 2 * AT_TILE +
                    (uint32_t)((ks * 16 + v_rsel) * AT_PAD + v_csel + j2 * 16) * 2;
                LDM_X4T(vh0, vh1, vh2, vh3, voff);
                LDM_X4T(vl0, vl1, vl2, vl3, voff + AT_TILE);
                MMA16816(oacc[2 * j2],     pah[ks], vh0, vh1);
                MMA16816(oacc[2 * j2],     pal[ks], vh0, vh1);
                MMA16816(oacc[2 * j2],     pah[ks], vl0, vl1);
                MMA16816(oacc[2 * j2 + 1], pah[ks], vh2, vh3);
                MMA16816(oacc[2 * j2 + 1], pal[ks], vh2, vh3);
                MMA16816(oacc[2 * j2 + 1], pah[ks], vl2, vl3);
            }
        }
        __syncthreads();
    }

    // ---- output: ctx bf16 hi/lo ----
    float inv0 = 1.0f / l0, inv1 = 1.0f / l1;
    int grow = qt * 128 + wid * 16 + gid;
    #pragma unroll
    for (int ni = 0; ni < 8; ++ni) {
        size_t i0 = (rowbase + grow) * (size_t)DMODEL + h * HDIM + ni * 8 + tig * 2;
        size_t i1 = i0 + 8 * (size_t)DMODEL;
        uint32_t hh, ll;
        split2(oacc[ni][0] * inv0, oacc[ni][1] * inv0, hh, ll);
        *(uint32_t*)&Oh[i0] = hh;
        *(uint32_t*)&Ol[i0] = ll;
        split2(oacc[ni][2] * inv1, oacc[ni][3] * inv1, hh, ll);
        *(uint32_t*)&Oh[i1] = hh;
        *(uint32_t*)&Ol[i1] = ll;
    }
}

// ---------------- launch -------------------------------------------
static void* sym_addr(const void* sym) {
    void* p = nullptr;
    cudaGetSymbolAddress(&p, sym);
    return p;
}

extern "C" void kernel_launch(void* const* d_in, const int* in_sizes, int n_in,
                              void* d_out, int out_size) {
    const float* x     = (const float*)d_in[0];
    const float* ln1_g = (const float*)d_in[1];
    const float* ln1_b = (const float*)d_in[2];
    const float* Wq    = (const float*)d_in[3];
    const float* Wk    = (const float*)d_in[4];
    const float* Wv    = (const float*)d_in[5];
    const float* Wo    = (const float*)d_in[6];
    const float* ln2_g = (const float*)d_in[7];
    const float* ln2_b = (const float*)d_in[8];
    const float* W1    = (const float*)d_in[9];
    const float* b1    = (const float*)d_in[10];
    const float* W2    = (const float*)d_in[11];
    const float* b2    = (const float*)d_in[12];
    float* out = (float*)d_out;

    float* x2 = (float*)sym_addr(g_x2);
    __nv_bfloat16* lnh   = (__nv_bfloat16*)sym_addr(g_lnh);
    __nv_bfloat16* lnl   = (__nv_bfloat16*)sym_addr(g_lnl);
    __nv_bfloat16* qkvh  = (__nv_bfloat16*)sym_addr(g_qkvh);
    __nv_bfloat16* qkvl  = (__nv_bfloat16*)sym_addr(g_qkvl);
    __nv_bfloat16* ctxh  = (__nv_bfloat16*)sym_addr(g_ctxh);
    __nv_bfloat16* ctxl  = (__nv_bfloat16*)sym_addr(g_ctxl);
    __nv_bfloat16* ffh   = (__nv_bfloat16*)sym_addr(g_ffh);
    __nv_bfloat16* ffl   = (__nv_bfloat16*)sym_addr(g_ffl);

    __nv_bfloat16* Bqkv_h = (__nv_bfloat16*)sym_addr(g_Bqkv_h);
    __nv_bfloat16* Bqkv_l = (__nv_bfloat16*)sym_addr(g_Bqkv_l);
    __nv_bfloat16* Bo_h = (__nv_bfloat16*)sym_addr(g_Bo_h);
    __nv_bfloat16* Bo_l = (__nv_bfloat16*)sym_addr(g_Bo_l);
    __nv_bfloat16* B1_h = (__nv_bfloat16*)sym_addr(g_B1_h);
    __nv_bfloat16* B1_l = (__nv_bfloat16*)sym_addr(g_B1_l);
    __nv_bfloat16* B2_h = (__nv_bfloat16*)sym_addr(g_B2_h);
    __nv_bfloat16* B2_l = (__nv_bfloat16*)sym_addr(g_B2_l);

    cudaFuncSetAttribute(hgemm_kernel<0, 0, 0, 1>,
                         cudaFuncAttributeMaxDynamicSharedMemorySize, HG_SMEM_BYTES);
    cudaFuncSetAttribute(hgemm_kernel<0, 0, 1, 0>,
                         cudaFuncAttributeMaxDynamicSharedMemorySize, HG_SMEM_BYTES);
    cudaFuncSetAttribute(hgemm_kernel<1, 1, 0, 1>,
                         cudaFuncAttributeMaxDynamicSharedMemorySize, HG_SMEM_BYTES);
    cudaFuncSetAttribute(hgemm_kernel<0, 1, 1, 0>,
                         cudaFuncAttributeMaxDynamicSharedMemorySize, HG_SMEM_BYTES);
    cudaFuncSetAttribute(attn_kernel,
                         cudaFuncAttributeMaxDynamicSharedMemorySize, AT_SMEM);

    dim3 blk256(256);
    dim3 gqkv(DM3 / 128, MROWS / 128);         // (24, 32)
    dim3 g1k(DMODEL / 128, MROWS / 128);       // (8, 32)
    dim3 g2k(2 * DMODEL / 128, MROWS / 128);   // (16, 32)

    // 0: weight prep
    wsplit_all_kernel<<<8192, blk256>>>(Wq, Wk, Wv, Bqkv_h, Bqkv_l,
                                        Wo, Bo_h, Bo_l,
                                        W1, B1_h, B1_l, W2, B2_h, B2_l);
    // 1: LN1
    ln_kernel<<<MROWS, blk256>>>(x, ln1_g, ln1_b, lnh, lnl);
    // 2: merged QKV projection
    hgemm_kernel<0, 0, 0, 1><<<gqkv, blk256, HG_SMEM_BYTES>>>(
        lnh, lnl, Bqkv_h, Bqkv_l, nullptr, nullptr, nullptr, qkvh, qkvl,
        MROWS, DM3, DMODEL);
    // 3: attention (256 thr, 128q x 64k)
    attn_kernel<<<dim3(16, 32), blk256, AT_SMEM>>>(qkvh, qkvl, ctxh, ctxl);
    // 4: output projection + residual(x)
    hgemm_kernel<0, 0, 1, 0><<<g1k, blk256, HG_SMEM_BYTES>>>(
        ctxh, ctxl, Bo_h, Bo_l, nullptr, x, x2, nullptr, nullptr,
        MROWS, DMODEL, DMODEL);
    // 5: LN2
    ln_kernel<<<MROWS, blk256>>>(x2, ln2_g, ln2_b, lnh, lnl);
    // 6: FFN up + bias + GELU
    hgemm_kernel<1, 1, 0, 1><<<g2k, blk256, HG_SMEM_BYTES>>>(
        lnh, lnl, B1_h, B1_l, b1, nullptr, nullptr, ffh, ffl,
        MROWS, 2 * DMODEL, DMODEL);
    // 7: FFN down + bias + residual(x2) -> out
    hgemm_kernel<0, 1, 1, 0><<<g1k, blk256, HG_SMEM_BYTES>>>(
        ffh, ffl, B2_h, B2_l, b2, x2, out, nullptr, nullptr,
        MROWS, DMODEL, 2 * DMODEL);
}

// round 13
// speedup vs baseline: 1.0521x; 1.0521x over previous
#include <cuda_runtime.h>
#include <cuda_bf16.h>
#include <math.h>
#include <stdint.h>

#define DMODEL 1024
#define SEQT   2048
#define BATCH  2
#define MROWS  4096   // BATCH * SEQT
#define NHEAD  16
#define HDIM   64
#define DM3    (3 * DMODEL)

// ---------------- scratch (static device allocations) ----------------
__device__ float g_x2 [MROWS * DMODEL];
__device__ __nv_bfloat16 g_lnh [MROWS * DMODEL], g_lnl [MROWS * DMODEL];
__device__ __nv_bfloat16 g_qkvh[MROWS * DM3],    g_qkvl[MROWS * DM3];
__device__ __nv_bfloat16 g_ctxh[MROWS * DMODEL], g_ctxl[MROWS * DMODEL];
__device__ __nv_bfloat16 g_ffh [MROWS * 2 * DMODEL], g_ffl [MROWS * 2 * DMODEL];

__device__ __nv_bfloat16 g_Bqkv_h[DM3 * DMODEL], g_Bqkv_l[DM3 * DMODEL];
__device__ __nv_bfloat16 g_Bo_h[DMODEL * DMODEL], g_Bo_l[DMODEL * DMODEL];
__device__ __nv_bfloat16 g_B1_h[2 * DMODEL * DMODEL], g_B1_l[2 * DMODEL * DMODEL];
__device__ __nv_bfloat16 g_B2_h[2 * DMODEL * DMODEL], g_B2_l[2 * DMODEL * DMODEL];

// ---------------- helpers --------------------------------------------
__device__ __forceinline__ uint32_t smem_u32(const void* p) {
    uint32_t a;
    asm("{ .reg .u64 t; cvta.to.shared.u64 t, %1; cvt.u32.u64 %0, t; }"
        : "=r"(a) : "l"(p));
    return a;
}
__device__ __forceinline__ float gelu_exact(float x) {
    return 0.5f * x * (1.0f + erff(x * 0.70710678118654752f));
}
__device__ __forceinline__ void split2(float x, float y, uint32_t& h, uint32_t& l) {
    __nv_bfloat162 hh = __float22bfloat162_rn(make_float2(x, y));
    float2 f = __bfloat1622float2(hh);
    __nv_bfloat162 ll = __float22bfloat162_rn(make_float2(x - f.x, y - f.y));
    h = *(uint32_t*)&hh;
    l = *(uint32_t*)&ll;
}

#define LDM_X4(r0, r1, r2, r3, addr) \
    asm volatile("ldmatrix.sync.aligned.m8n8.x4.shared.b16 {%0,%1,%2,%3}, [%4];" \
        : "=r"(r0), "=r"(r1), "=r"(r2), "=r"(r3) : "r"(addr))
#define LDM_X4T(r0, r1, r2, r3, addr) \
    asm volatile("ldmatrix.sync.aligned.m8n8.x4.trans.shared.b16 {%0,%1,%2,%3}, [%4];" \
        : "=r"(r0), "=r"(r1), "=r"(r2), "=r"(r3) : "r"(addr))

#define MMA16816(d, a, b0, b1) \
    asm volatile("mma.sync.aligned.m16n8k16.row.col.f32.bf16.bf16.f32 " \
        "{%0,%1,%2,%3}, {%4,%5,%6,%7}, {%8,%9}, {%0,%1,%2,%3};" \
        : "+f"((d)[0]), "+f"((d)[1]), "+f"((d)[2]), "+f"((d)[3]) \
        : "r"((a)[0]), "r"((a)[1]), "r"((a)[2]), "r"((a)[3]), \
          "r"(b0), "r"(b1))

#define CP16(dst, src) \
    asm volatile("cp.async.cg.shared.global [%0], [%1], 16;" \
        :: "r"(dst), "l"(src))
#define CP_COMMIT() asm volatile("cp.async.commit_group;")
#define CP_WAIT2()  asm volatile("cp.async.wait_group 2;")
#define CP_WAIT1()  asm volatile("cp.async.wait_group 1;")
#define CP_WAIT0()  asm volatile("cp.async.wait_group 0;")

// 64B-row tile swizzle for GEMM smem.
#define SWZ64(off) ((off) ^ ((((off) >> 7) & 3u) << 4))
// 128B-row tile swizzle (standard SW128) for attention K/V smem.
#define SWZ128B(off) ((off) ^ (((off) >> 3) & 0x70u))

// ---------------- weight prep ----------------------------------------
__global__ void __launch_bounds__(256) wsplit_all_kernel(
    const float* __restrict__ Wq, const float* __restrict__ Wk,
    const float* __restrict__ Wv,
    __nv_bfloat16* __restrict__ Bqkv_h, __nv_bfloat16* __restrict__ Bqkv_l,
    const float* __restrict__ Wo, __nv_bfloat16* __restrict__ Bo_h, __nv_bfloat16* __restrict__ Bo_l,
    const float* __restrict__ W1, __nv_bfloat16* __restrict__ B1_h, __nv_bfloat16* __restrict__ B1_l,
    const float* __restrict__ W2, __nv_bfloat16* __restrict__ B2_h, __nv_bfloat16* __restrict__ B2_l) {
    __shared__ float t[32][33];
    int bid = blockIdx.x;
    const float* W;
    __nv_bfloat16 *Th, *Tl;
    int K, N, k0, n0, nout;
    if (bid < 4096) {
        int w = bid >> 10, lb = bid & 1023;
        K = DMODEL; N = DMODEL;
        k0 = (lb & 31) * 32; n0 = (lb >> 5) * 32;
        if (w < 3) {
            W = (w == 0) ? Wq : (w == 1) ? Wk : Wv;
            Th = Bqkv_h; Tl = Bqkv_l;
            nout = n0 + w * DMODEL;
        } else {
            W = Wo; Th = Bo_h; Tl = Bo_l; nout = n0;
        }
    } else if (bid < 6144) {
        int lb = bid - 4096;
        K = DMODEL; N = 2 * DMODEL;
        k0 = (lb & 31) * 32; n0 = (lb >> 5) * 32;
        W = W1; Th = B1_h; Tl = B1_l; nout = n0;
    } else {
        int lb = bid - 6144;
        K = 2 * DMODEL; N = DMODEL;
        k0 = (lb & 63) * 32; n0 = (lb >> 6) * 32;
        W = W2; Th = B2_h; Tl = B2_l; nout = n0;
    }
    int tx = threadIdx.x & 31, ty = threadIdx.x >> 5;
    #pragma unroll
    for (int i = 0; i < 4; ++i)
        t[ty + i * 8][tx] = W[(size_t)(k0 + ty + i * 8) * N + n0 + tx];
    __syncthreads();
    #pragma unroll
    for (int i = 0; i < 4; ++i) {
        int n = nout + ty + i * 8, k = k0 + tx;
        float x = t[tx][ty + i * 8];
        __nv_bfloat16 h = __float2bfloat16_rn(x);
        float lo = x - __bfloat162float(h);
        Th[(size_t)n * K + k] = h;
        Tl[(size_t)n * K + k] = __float2bfloat16_rn(lo);
    }
}

// ---------------- LayerNorm -> bf16 hi/lo ----------------------------
__global__ void __launch_bounds__(256) ln_kernel(const float* __restrict__ x,
                                                 const float* __restrict__ g,
                                                 const float* __restrict__ b,
                                                 __nv_bfloat16* __restrict__ outh,
                                                 __nv_bfloat16* __restrict__ outl) {
    int row = blockIdx.x;
    int tid = threadIdx.x;
    const float4* xr = (const float4*)(x + (size_t)row * DMODEL);
    float4 v = xr[tid];
    float s  = v.x + v.y + v.z + v.w;
    float ss = v.x * v.x + v.y * v.y + v.z * v.z + v.w * v.w;
    #pragma unroll
    for (int o = 16; o > 0; o >>= 1) {
        s  += __shfl_xor_sync(0xffffffffu, s,  o);
        ss += __shfl_xor_sync(0xffffffffu, ss, o);
    }
    __shared__ float sh[16];
    int w = tid >> 5;
    if ((tid & 31) == 0) { sh[w] = s; sh[8 + w] = ss; }
    __syncthreads();
    if (tid < 32) {
        float a  = (tid < 8) ? sh[tid]     : 0.0f;
        float a2 = (tid < 8) ? sh[8 + tid] : 0.0f;
        #pragma unroll
        for (int o = 4; o > 0; o >>= 1) {
            a  += __shfl_xor_sync(0xffffffffu, a,  o);
            a2 += __shfl_xor_sync(0xffffffffu, a2, o);
        }
        if (tid == 0) { sh[0] = a; sh[1] = a2; }
    }
    __syncthreads();
    float mean = sh[0] * (1.0f / DMODEL);
    float var  = sh[1] * (1.0f / DMODEL) - mean * mean;
    float rstd = rsqrtf(var + 1e-5f);
    float4 gg = ((const float4*)g)[tid];
    float4 bb = ((const float4*)b)[tid];
    float o0 = (v.x - mean) * rstd * gg.x + bb.x;
    float o1 = (v.y - mean) * rstd * gg.y + bb.y;
    float o2 = (v.z - mean) * rstd * gg.z + bb.z;
    float o3 = (v.w - mean) * rstd * gg.w + bb.w;
    uint2 h, l;
    split2(o0, o1, h.x, l.x);
    split2(o2, o3, h.y, l.y);
    ((uint2*)(outh + (size_t)row * DMODEL))[tid] = h;
    ((uint2*)(outl + (size_t)row * DMODEL))[tid] = l;
}

// ---------------- HMMA GEMM (r11 proven): 256 thr, 3-stage swizzled --
#define HG_A_L   8192
#define HG_B     16384
#define HG_B_L   8192
#define HG_STAGE 32768
#define HG_SMEM_BYTES (3 * HG_STAGE)

template <int GELU, int HAS_BIAS, int HAS_RES, int OSPLIT>
__global__ void __launch_bounds__(256, 2) hgemm_kernel(
    const __nv_bfloat16* __restrict__ Ah, const __nv_bfloat16* __restrict__ Al,
    const __nv_bfloat16* __restrict__ Bh, const __nv_bfloat16* __restrict__ Bl,
    const float* __restrict__ bias, const float* __restrict__ res,
    float* __restrict__ C, __nv_bfloat16* __restrict__ Ch,
    __nv_bfloat16* __restrict__ Cl, int M, int N, int K) {
    extern __shared__ __align__(16) char smem[];
    uint32_t uS = smem_u32(smem);

    int tid = threadIdx.x;
    int lane = tid & 31, wid = tid >> 5;
    int wm = wid >> 2, wn = wid & 3;
    int bm = blockIdx.y * 128, bn = blockIdx.x * 128;

    float acc[4][4][4];
    #pragma unroll
    for (int i = 0; i < 4; ++i)
        #pragma unroll
        for (int j = 0; j < 4; ++j)
            #pragma unroll
            for (int k = 0; k < 4; ++k) acc[i][j][k] = 0.0f;

    int q = lane >> 3, rr = lane & 7;
    int a_row = wm * 64 + (q & 1) * 8 + rr;
    int a_cb  = 16 * (q >> 1);
    int b_row = wn * 32 + (q >> 1) * 8 + rr;
    int b_cb  = 16 * (q & 1);

    int lr = tid >> 2, lck = (tid & 3) << 4;
    const int NC = K >> 5;

    auto load_chunk = [&](int c, int s) {
        uint32_t sb = uS + (uint32_t)s * HG_STAGE;
        int kc = c << 5;
        #pragma unroll
        for (int i = 0; i < 2; ++i) {
            int r = lr + i * 64;
            uint32_t d = sb + SWZ64((uint32_t)(r * 64 + lck));
            CP16(d, Ah + (size_t)(bm + r) * K + kc + (lck >> 1));
            CP16(d + HG_A_L, Al + (size_t)(bm + r) * K + kc + (lck >> 1));
        }
        #pragma unroll
        for (int i = 0; i < 2; ++i) {
            int r = lr + i * 64;
            uint32_t d = sb + HG_B + SWZ64((uint32_t)(r * 64 + lck));
            CP16(d, Bh + (size_t)(bn + r) * K + kc + (lck >> 1));
            CP16(d + HG_B_L, Bl + (size_t)(bn + r) * K + kc + (lck >> 1));
        }
        CP_COMMIT();
    };

    load_chunk(0, 0);
    if (NC > 1) load_chunk(1, 1);

    for (int c = 0; c < NC; ++c) {
        if (c + 2 < NC) { load_chunk(c + 2, (c + 2) % 3); CP_WAIT2(); }
        else if (c + 1 < NC) { CP_WAIT1(); }
        else { CP_WAIT0(); }
        __syncthreads();

        uint32_t sb = uS + (uint32_t)(c % 3) * HG_STAGE;
        #pragma unroll
        for (int ks = 0; ks < 2; ++ks) {
            uint32_t ahf[4][4], alf[4][4];
            #pragma unroll
            for (int mi = 0; mi < 4; ++mi) {
                uint32_t off = sb + SWZ64(
                    (uint32_t)((a_row + mi * 16) * 64 + a_cb + ks * 32));
                LDM_X4(ahf[mi][0], ahf[mi][1], ahf[mi][2], ahf[mi][3], off);
                LDM_X4(alf[mi][0], alf[mi][1], alf[mi][2], alf[mi][3], off + HG_A_L);
            }
            #pragma unroll
            for (int j2 = 0; j2 < 2; ++j2) {
                uint32_t bhf[2][2], blf[2][2];
                uint32_t off = sb + HG_B + SWZ64(
                    (uint32_t)((b_row + j2 * 16) * 64 + b_cb + ks * 32));
                LDM_X4(bhf[0][0], bhf[0][1], bhf[1][0], bhf[1][1], off);
                LDM_X4(blf[0][0], blf[0][1], blf[1][0], blf[1][1], off + HG_B_L);
                #pragma unroll
                for (int mi = 0; mi < 4; ++mi)
                    #pragma unroll
                    for (int nj = 0; nj < 2; ++nj) {
                        int ni = j2 * 2 + nj;
                        MMA16816(acc[mi][ni], ahf[mi], bhf[nj][0], bhf[nj][1]);
                        MMA16816(acc[mi][ni], alf[mi], bhf[nj][0], bhf[nj][1]);
                        MMA16816(acc[mi][ni], ahf[mi], blf[nj][0], blf[nj][1]);
                    }
            }
        }
        __syncthreads();
    }

    int gid = lane >> 2, tig = lane & 3;
    #pragma unroll
    for (int mi = 0; mi < 4; ++mi) {
        #pragma unroll
        for (int ni = 0; ni < 4; ++ni) {
            int row0 = bm + wm * 64 + mi * 16 + gid;
            int col  = bn + wn * 32 + ni * 8 + tig * 2;
            float c0 = acc[mi][ni][0], c1 = acc[mi][ni][1];
            float c2 = acc[mi][ni][2], c3 = acc[mi][ni][3];
            if (HAS_BIAS) {
                float b0 = bias[col], b1v = bias[col + 1];
                c0 += b0; c1 += b1v; c2 += b0; c3 += b1v;
            }
            if (GELU) {
                c0 = gelu_exact(c0); c1 = gelu_exact(c1);
                c2 = gelu_exact(c2); c3 = gelu_exact(c3);
            }
            if (HAS_RES) {
                float2 r0 = *(const float2*)&res[(size_t)row0 * N + col];
                float2 r1 = *(const float2*)&res[(size_t)(row0 + 8) * N + col];
                c0 += r0.x; c1 += r0.y; c2 += r1.x; c3 += r1.y;
            }
            if (OSPLIT) {
                uint32_t h0, l0, h1, l1;
                split2(c0, c1, h0, l0);
                split2(c2, c3, h1, l1);
                *(uint32_t*)&Ch[(size_t)row0 * N + col] = h0;
                *(uint32_t*)&Cl[(size_t)row0 * N + col] = l0;
                *(uint32_t*)&Ch[(size_t)(row0 + 8) * N + col] = h1;
                *(uint32_t*)&Cl[(size_t)(row0 + 8) * N + col] = l1;
            } else {
                float2 o0; o0.x = c0; o0.y = c1;
                float2 o1; o1.x = c2; o1.y = c3;
                *(float2*)&C[(size_t)row0 * N + col] = o0;
                *(float2*)&C[(size_t)(row0 + 8) * N + col] = o1;
            }
        }
    }
}

// ---------------- Tensor-core flash attention -------------------------
// r11 shape (64q x 64k, 4 warps, 128 thr) with two changes:
//  - Q fragments hoisted to registers (loaded from gmem once; no Q smem)
//  - K/V smem pad-free SW128-swizzled 128B rows: stage 32KB, 2 stages
//    = 64KB total -> 3 CTAs/SM (12 warps).
#define AT_TILE  8192
#define AT_STAGE 32768
#define AT_SMEM  (2 * AT_STAGE)  // 65536

__global__ void __launch_bounds__(128, 3) attn_kernel(
    const __nv_bfloat16* __restrict__ QKVh, const __nv_bfloat16* __restrict__ QKVl,
    __nv_bfloat16* __restrict__ Oh, __nv_bfloat16* __restrict__ Ol) {
    extern __shared__ __align__(16) char smem[];
    uint32_t uS = smem_u32(smem);

    int qt = 31 - (int)blockIdx.x;   // heavy-first
    int bh = blockIdx.y;
    int b = bh >> 4, h = bh & 15;
    int tid = threadIdx.x, lane = tid & 31, wid = tid >> 5;
    int gid = lane >> 2, tig = lane & 3;
    int q = lane >> 3, rr = lane & 7;

    size_t rowbase = (size_t)b * SEQT;

    // K/V tile loader: 64 rows x 128B, SW128 swizzled within tile.
    auto ld_kv = [&](const __nv_bfloat16* G, uint32_t dst, int trow, int cbase) {
        #pragma unroll
        for (int i = 0; i < 4; ++i) {
            int idx = tid + i * 128;
            int r = idx >> 3, c8 = (idx & 7) << 3;
            CP16(dst + SWZ128B((uint32_t)(r * 128 + c8 * 2)),
                 G + (rowbase + trow + r) * (size_t)DM3 + cbase + h * HDIM + c8);
        }
    };

    // prologue: KV tile 0
    ld_kv(QKVh, uS, 0, DMODEL);
    ld_kv(QKVl, uS + AT_TILE, 0, DMODEL);
    ld_kv(QKVh, uS + 2 * AT_TILE, 0, 2 * DMODEL);
    ld_kv(QKVl, uS + 3 * AT_TILE, 0, 2 * DMODEL);
    CP_COMMIT();

    // Q fragments: loaded once, directly from gmem (A-frag thread mapping:
    // lane holds rows gid/gid+8, cols 2*tig and 2*tig+8, per 16x16 k-step).
    uint32_t qh[4][4], ql[4][4];
    {
        int row0 = qt * 64 + wid * 16 + gid;
        size_t base0 = (rowbase + row0) * (size_t)DM3 + h * HDIM;
        size_t base8 = base0 + 8 * (size_t)DM3;
        #pragma unroll
        for (int ks = 0; ks < 4; ++ks) {
            int c0 = ks * 16 + 2 * tig;
            qh[ks][0] = *(const uint32_t*)&QKVh[base0 + c0];
            qh[ks][1] = *(const uint32_t*)&QKVh[base8 + c0];
            qh[ks][2] = *(const uint32_t*)&QKVh[base0 + c0 + 8];
            qh[ks][3] = *(const uint32_t*)&QKVh[base8 + c0 + 8];
            ql[ks][0] = *(const uint32_t*)&QKVl[base0 + c0];
            ql[ks][1] = *(const uint32_t*)&QKVl[base8 + c0];
            ql[ks][2] = *(const uint32_t*)&QKVl[base0 + c0 + 8];
            ql[ks][3] = *(const uint32_t*)&QKVl[base8 + c0 + 8];
        }
    }

    float oacc[8][4];
    #pragma unroll
    for (int i = 0; i < 8; ++i)
        #pragma unroll
        for (int j = 0; j < 4; ++j) oacc[i][j] = 0.0f;
    float m0 = -1e30f, m1 = -1e30f, l0 = 0.0f, l1 = 0.0f;

    int b_rsel = (q >> 1) * 8 + rr;  // + j2*16
    int b_csel = (q & 1) * 8;        // + ks*16
    int v_rsel = (q & 1) * 8 + rr;   // + ks*16
    int v_csel = (q >> 1) * 8;       // + j2*16

    for (int kt = 0; kt <= qt; ++kt) {
        uint32_t st = uS + (uint32_t)(kt & 1) * AT_STAGE;
        if (kt < qt) {
            uint32_t s2 = uS + (uint32_t)((kt + 1) & 1) * AT_STAGE;
            ld_kv(QKVh, s2, (kt + 1) * 64, DMODEL);
            ld_kv(QKVl, s2 + AT_TILE, (kt + 1) * 64, DMODEL);
            ld_kv(QKVh, s2 + 2 * AT_TILE, (kt + 1) * 64, 2 * DMODEL);
            ld_kv(QKVl, s2 + 3 * AT_TILE, (kt + 1) * 64, 2 * DMODEL);
            CP_COMMIT();
            CP_WAIT1();
        } else {
            CP_WAIT0();
        }
        __syncthreads();

        // ---- S = Q K^T (3-product split) ----
        float sc[8][4];
        #pragma unroll
        for (int i = 0; i < 8; ++i)
            #pragma unroll
            for (int j = 0; j < 4; ++j) sc[i][j] = 0.0f;

        #pragma unroll
        for (int ks = 0; ks < 4; ++ks) {
            #pragma unroll
            for (int j2 = 0; j2 < 4; ++j2) {
                uint32_t kh0, kh1, kh2, kh3, kl0, kl1, kl2, kl3;
                uint32_t boff = st + SWZ128B(
                    (uint32_t)((j2 * 16 + b_rsel) * 128 + (b_csel + ks * 16) * 2));
                LDM_X4(kh0, kh1, kh2, kh3, boff);
                LDM_X4(kl0, kl1, kl2, kl3, boff + AT_TILE);
                MMA16816(sc[2 * j2],     qh[ks], kh0, kh1);
                MMA16816(sc[2 * j2],     ql[ks], kh0, kh1);
                MMA16816(sc[2 * j2],     qh[ks], kl0, kl1);
                MMA16816(sc[2 * j2 + 1], qh[ks], kh2, kh3);
                MMA16816(sc[2 * j2 + 1], ql[ks], kh2, kh3);
                MMA16816(sc[2 * j2 + 1], qh[ks], kl2, kl3);
            }
        }

        // scale + causal mask
        #pragma unroll
        for (int ni = 0; ni < 8; ++ni) {
            sc[ni][0] *= 0.125f; sc[ni][1] *= 0.125f;
            sc[ni][2] *= 0.125f; sc[ni][3] *= 0.125f;
        }
        if (kt == qt) {
            int r0 = wid * 16 + gid, r1 = r0 + 8;
            #pragma unroll
            for (int ni = 0; ni < 8; ++ni) {
                int c0 = ni * 8 + tig * 2, c1 = c0 + 1;
                if (c0 > r0) sc[ni][0] = -1e30f;
                if (c1 > r0) sc[ni][1] = -1e30f;
                if (c0 > r1) sc[ni][2] = -1e30f;
                if (c1 > r1) sc[ni][3] = -1e30f;
            }
        }

        // ---- online softmax in registers ----
        float t0 = -1e30f, t1 = -1e30f;
        #pragma unroll
        for (int ni = 0; ni < 8; ++ni) {
            t0 = fmaxf(t0, fmaxf(sc[ni][0], sc[ni][1]));
            t1 = fmaxf(t1, fmaxf(sc[ni][2], sc[ni][3]));
        }
        t0 = fmaxf(t0, __shfl_xor_sync(0xffffffffu, t0, 1));
        t0 = fmaxf(t0, __shfl_xor_sync(0xffffffffu, t0, 2));
        t1 = fmaxf(t1, __shfl_xor_sync(0xffffffffu, t1, 1));
        t1 = fmaxf(t1, __shfl_xor_sync(0xffffffffu, t1, 2));
        float mn0 = fmaxf(m0, t0), mn1 = fmaxf(m1, t1);
        float al0 = __expf(m0 - mn0), al1 = __expf(m1 - mn1);
        m0 = mn0; m1 = mn1;

        float sum0 = 0.0f, sum1 = 0.0f;
        uint32_t pah[4][4], pal[4][4];
        #pragma unroll
        for (int kp = 0; kp < 4; ++kp) {
            float p00 = __expf(sc[2 * kp][0] - mn0);
            float p01 = __expf(sc[2 * kp][1] - mn0);
            float p02 = __expf(sc[2 * kp][2] - mn1);
            float p03 = __expf(sc[2 * kp][3] - mn1);
            float p10 = __expf(sc[2 * kp + 1][0] - mn0);
            float p11 = __expf(sc[2 * kp + 1][1] - mn0);
            float p12 = __expf(sc[2 * kp + 1][2] - mn1);
            float p13 = __expf(sc[2 * kp + 1][3] - mn1);
            sum0 += p00 + p01 + p10 + p11;
            sum1 += p02 + p03 + p12 + p13;
            split2(p00, p01, pah[kp][0], pal[kp][0]);
            split2(p02, p03, pah[kp][1], pal[kp][1]);
            split2(p10, p11, pah[kp][2], pal[kp][2]);
            split2(p12, p13, pah[kp][3], pal[kp][3]);
        }
        sum0 += __shfl_xor_sync(0xffffffffu, sum0, 1);
        sum0 += __shfl_xor_sync(0xffffffffu, sum0, 2);
        sum1 += __shfl_xor_sync(0xffffffffu, sum1, 1);
        sum1 += __shfl_xor_sync(0xffffffffu, sum1, 2);
        l0 = l0 * al0 + sum0;
        l1 = l1 * al1 + sum1;
        #pragma unroll
        for (int ni = 0; ni < 8; ++ni) {
            oacc[ni][0] *= al0; oacc[ni][1] *= al0;
            oacc[ni][2] *= al1; oacc[ni][3] *= al1;
        }

        // ---- O += P V (V via trans-ldmatrix) ----
        #pragma unroll
        for (int ks = 0; ks < 4; ++ks) {
            #pragma unroll
            for (int j2 = 0; j2 < 4; ++j2) {
                uint32_t vh0, vh1, vh2, vh3, vl0, vl1, vl2, vl3;
                uint32_t voff = st + 2 * AT_TILE + SWZ128B(
                    (uint32_t)((ks * 16 + v_rsel) * 128 + (v_csel + j2 * 16) * 2));
                LDM_X4T(vh0, vh1, vh2, vh3, voff);
                LDM_X4T(vl0, vl1, vl2, vl3, voff + AT_TILE);
                MMA16816(oacc[2 * j2],     pah[ks], vh0, vh1);
                MMA16816(oacc[2 * j2],     pal[ks], vh0, vh1);
                MMA16816(oacc[2 * j2],     pah[ks], vl0, vl1);
                MMA16816(oacc[2 * j2 + 1], pah[ks], vh2, vh3);
                MMA16816(oacc[2 * j2 + 1], pal[ks], vh2, vh3);
                MMA16816(oacc[2 * j2 + 1], pah[ks], vl2, vl3);
            }
        }
        __syncthreads();
    }

    // ---- output: ctx bf16 hi/lo ----
    float inv0 = 1.0f / l0, inv1 = 1.0f / l1;
    int grow = qt * 64 + wid * 16 + gid;
    #pragma unroll
    for (int ni = 0; ni < 8; ++ni) {
        size_t i0 = (rowbase + grow) * (size_t)DMODEL + h * HDIM + ni * 8 + tig * 2;
        size_t i1 = i0 + 8 * (size_t)DMODEL;
        uint32_t hh, ll;
        split2(oacc[ni][0] * inv0, oacc[ni][1] * inv0, hh, ll);
        *(uint32_t*)&Oh[i0] = hh;
        *(uint32_t*)&Ol[i0] = ll;
        split2(oacc[ni][2] * inv1, oacc[ni][3] * inv1, hh, ll);
        *(uint32_t*)&Oh[i1] = hh;
        *(uint32_t*)&Ol[i1] = ll;
    }
}

// ---------------- launch -------------------------------------------
static void* sym_addr(const void* sym) {
    void* p = nullptr;
    cudaGetSymbolAddress(&p, sym);
    return p;
}

extern "C" void kernel_launch(void* const* d_in, const int* in_sizes, int n_in,
                              void* d_out, int out_size) {
    const float* x     = (const float*)d_in[0];
    const float* ln1_g = (const float*)d_in[1];
    const float* ln1_b = (const float*)d_in[2];
    const float* Wq    = (const float*)d_in[3];
    const float* Wk    = (const float*)d_in[4];
    const float* Wv    = (const float*)d_in[5];
    const float* Wo    = (const float*)d_in[6];
    const float* ln2_g = (const float*)d_in[7];
    const float* ln2_b = (const float*)d_in[8];
    const float* W1    = (const float*)d_in[9];
    const float* b1    = (const float*)d_in[10];
    const float* W2    = (const float*)d_in[11];
    const float* b2    = (const float*)d_in[12];
    float* out = (float*)d_out;

    float* x2 = (float*)sym_addr(g_x2);
    __nv_bfloat16* lnh   = (__nv_bfloat16*)sym_addr(g_lnh);
    __nv_bfloat16* lnl   = (__nv_bfloat16*)sym_addr(g_lnl);
    __nv_bfloat16* qkvh  = (__nv_bfloat16*)sym_addr(g_qkvh);
    __nv_bfloat16* qkvl  = (__nv_bfloat16*)sym_addr(g_qkvl);
    __nv_bfloat16* ctxh  = (__nv_bfloat16*)sym_addr(g_ctxh);
    __nv_bfloat16* ctxl  = (__nv_bfloat16*)sym_addr(g_ctxl);
    __nv_bfloat16* ffh   = (__nv_bfloat16*)sym_addr(g_ffh);
    __nv_bfloat16* ffl   = (__nv_bfloat16*)sym_addr(g_ffl);

    __nv_bfloat16* Bqkv_h = (__nv_bfloat16*)sym_addr(g_Bqkv_h);
    __nv_bfloat16* Bqkv_l = (__nv_bfloat16*)sym_addr(g_Bqkv_l);
    __nv_bfloat16* Bo_h = (__nv_bfloat16*)sym_addr(g_Bo_h);
    __nv_bfloat16* Bo_l = (__nv_bfloat16*)sym_addr(g_Bo_l);
    __nv_bfloat16* B1_h = (__nv_bfloat16*)sym_addr(g_B1_h);
    __nv_bfloat16* B1_l = (__nv_bfloat16*)sym_addr(g_B1_l);
    __nv_bfloat16* B2_h = (__nv_bfloat16*)sym_addr(g_B2_h);
    __nv_bfloat16* B2_l = (__nv_bfloat16*)sym_addr(g_B2_l);

    cudaFuncSetAttribute(hgemm_kernel<0, 0, 0, 1>,
                         cudaFuncAttributeMaxDynamicSharedMemorySize, HG_SMEM_BYTES);
    cudaFuncSetAttribute(hgemm_kernel<0, 0, 1, 0>,
                         cudaFuncAttributeMaxDynamicSharedMemorySize, HG_SMEM_BYTES);
    cudaFuncSetAttribute(hgemm_kernel<1, 1, 0, 1>,
                         cudaFuncAttributeMaxDynamicSharedMemorySize, HG_SMEM_BYTES);
    cudaFuncSetAttribute(hgemm_kernel<0, 1, 1, 0>,
                         cudaFuncAttributeMaxDynamicSharedMemorySize, HG_SMEM_BYTES);
    cudaFuncSetAttribute(attn_kernel,
                         cudaFuncAttributeMaxDynamicSharedMemorySize, AT_SMEM);

    dim3 blk128(128), blk256(256);
    dim3 gqkv(DM3 / 128, MROWS / 128);         // (24, 32)
    dim3 g1k(DMODEL / 128, MROWS / 128);       // (8, 32)
    dim3 g2k(2 * DMODEL / 128, MROWS / 128);   // (16, 32)

    // 0: weight prep
    wsplit_all_kernel<<<8192, blk256>>>(Wq, Wk, Wv, Bqkv_h, Bqkv_l,
                                        Wo, Bo_h, Bo_l,
                                        W1, B1_h, B1_l, W2, B2_h, B2_l);
    // 1: LN1
    ln_kernel<<<MROWS, blk256>>>(x, ln1_g, ln1_b, lnh, lnl);
    // 2: merged QKV projection
    hgemm_kernel<0, 0, 0, 1><<<gqkv, blk256, HG_SMEM_BYTES>>>(
        lnh, lnl, Bqkv_h, Bqkv_l, nullptr, nullptr, nullptr, qkvh, qkvl,
        MROWS, DM3, DMODEL);
    // 3: attention (64q x 64k, Q-in-regs, 3 CTAs/SM)
    attn_kernel<<<dim3(32, 32), blk128, AT_SMEM>>>(qkvh, qkvl, ctxh, ctxl);
    // 4: output projection + residual(x)
    hgemm_kernel<0, 0, 1, 0><<<g1k, blk256, HG_SMEM_BYTES>>>(
        ctxh, ctxl, Bo_h, Bo_l, nullptr, x, x2, nullptr, nullptr,
        MROWS, DMODEL, DMODEL);
    // 5: LN2
    ln_kernel<<<MROWS, blk256>>>(x2, ln2_g, ln2_b, lnh, lnl);
    // 6: FFN up + bias + GELU
    hgemm_kernel<1, 1, 0, 1><<<g2k, blk256, HG_SMEM_BYTES>>>(
        lnh, lnl, B1_h, B1_l, b1, nullptr, nullptr, ffh, ffl,
        MROWS, 2 * DMODEL, DMODEL);
    // 7: FFN down + bias + residual(x2) -> out
    hgemm_kernel<0, 1, 1, 0><<<g1k, blk256, HG_SMEM_BYTES>>>(
        ffh, ffl, B2_h, B2_l, b2, x2, out, nullptr, nullptr,
        MROWS, DMODEL, 2 * DMODEL);
}

// round 14
// speedup vs baseline: 1.1255x; 1.0698x over previous
#include <cuda_runtime.h>
#include <cuda_bf16.h>
#include <cuda_fp16.h>
#include <math.h>
#include <stdint.h>

#define DMODEL 1024
#define SEQT   2048
#define BATCH  2
#define MROWS  4096   // BATCH * SEQT
#define NHEAD  16
#define HDIM   64
#define DM3    (3 * DMODEL)

// ---------------- scratch (static device allocations) ----------------
__device__ float g_x2 [MROWS * DMODEL];
__device__ __nv_bfloat16 g_lnh [MROWS * DMODEL], g_lnl [MROWS * DMODEL];
__device__ __half        g_qkvh[MROWS * DM3],    g_qkvl[MROWS * DM3];
__device__ __nv_bfloat16 g_ctxh[MROWS * DMODEL], g_ctxl[MROWS * DMODEL];
__device__ __nv_bfloat16 g_ffh [MROWS * 2 * DMODEL], g_ffl [MROWS * 2 * DMODEL];

__device__ __nv_bfloat16 g_Bqkv_h[DM3 * DMODEL], g_Bqkv_l[DM3 * DMODEL];
__device__ __nv_bfloat16 g_Bo_h[DMODEL * DMODEL], g_Bo_l[DMODEL * DMODEL];
__device__ __nv_bfloat16 g_B1_h[2 * DMODEL * DMODEL], g_B1_l[2 * DMODEL * DMODEL];
__device__ __nv_bfloat16 g_B2_h[2 * DMODEL * DMODEL], g_B2_l[2 * DMODEL * DMODEL];

// ---------------- helpers --------------------------------------------
__device__ __forceinline__ uint32_t smem_u32(const void* p) {
    uint32_t a;
    asm("{ .reg .u64 t; cvta.to.shared.u64 t, %1; cvt.u32.u64 %0, t; }"
        : "=r"(a) : "l"(p));
    return a;
}
__device__ __forceinline__ float gelu_exact(float x) {
    return 0.5f * x * (1.0f + erff(x * 0.70710678118654752f));
}
// bf16 hi/lo split
__device__ __forceinline__ void split2(float x, float y, uint32_t& h, uint32_t& l) {
    __nv_bfloat162 hh = __float22bfloat162_rn(make_float2(x, y));
    float2 f = __bfloat1622float2(hh);
    __nv_bfloat162 ll = __float22bfloat162_rn(make_float2(x - f.x, y - f.y));
    h = *(uint32_t*)&hh;
    l = *(uint32_t*)&ll;
}
// fp16 hi/lo split
__device__ __forceinline__ void split2h(float x, float y, uint32_t& h, uint32_t& l) {
    __half2 hh = __float22half2_rn(make_float2(x, y));
    float2 f = __half22float2(hh);
    __half2 ll = __float22half2_rn(make_float2(x - f.x, y - f.y));
    h = *(uint32_t*)&hh;
    l = *(uint32_t*)&ll;
}

#define LDM_X4(r0, r1, r2, r3, addr) \
    asm volatile("ldmatrix.sync.aligned.m8n8.x4.shared.b16 {%0,%1,%2,%3}, [%4];" \
        : "=r"(r0), "=r"(r1), "=r"(r2), "=r"(r3) : "r"(addr))
#define LDM_X4T(r0, r1, r2, r3, addr) \
    asm volatile("ldmatrix.sync.aligned.m8n8.x4.trans.shared.b16 {%0,%1,%2,%3}, [%4];" \
        : "=r"(r0), "=r"(r1), "=r"(r2), "=r"(r3) : "r"(addr))

// bf16 MMA (GEMMs)
#define MMA16816(d, a, b0, b1) \
    asm volatile("mma.sync.aligned.m16n8k16.row.col.f32.bf16.bf16.f32 " \
        "{%0,%1,%2,%3}, {%4,%5,%6,%7}, {%8,%9}, {%0,%1,%2,%3};" \
        : "+f"((d)[0]), "+f"((d)[1]), "+f"((d)[2]), "+f"((d)[3]) \
        : "r"((a)[0]), "r"((a)[1]), "r"((a)[2]), "r"((a)[3]), \
          "r"(b0), "r"(b1))
// fp16 MMA (attention)
#define MMAH16(d, a, b0, b1) \
    asm volatile("mma.sync.aligned.m16n8k16.row.col.f32.f16.f16.f32 " \
        "{%0,%1,%2,%3}, {%4,%5,%6,%7}, {%8,%9}, {%0,%1,%2,%3};" \
        : "+f"((d)[0]), "+f"((d)[1]), "+f"((d)[2]), "+f"((d)[3]) \
        : "r"((a)[0]), "r"((a)[1]), "r"((a)[2]), "r"((a)[3]), \
          "r"(b0), "r"(b1))

#define CP16(dst, src) \
    asm volatile("cp.async.cg.shared.global [%0], [%1], 16;" \
        :: "r"(dst), "l"(src))
#define CP_COMMIT() asm volatile("cp.async.commit_group;")
#define CP_WAIT2()  asm volatile("cp.async.wait_group 2;")
#define CP_WAIT1()  asm volatile("cp.async.wait_group 1;")
#define CP_WAIT0()  asm volatile("cp.async.wait_group 0;")

// 64B-row tile swizzle for GEMM smem.
#define SWZ64(off) ((off) ^ ((((off) >> 7) & 3u) << 4))
// 128B-row tile swizzle (standard SW128) for attention K/V smem.
#define SWZ128B(off) ((off) ^ (((off) >> 3) & 0x70u))

// ---------------- weight prep ----------------------------------------
__global__ void __launch_bounds__(256) wsplit_all_kernel(
    const float* __restrict__ Wq, const float* __restrict__ Wk,
    const float* __restrict__ Wv,
    __nv_bfloat16* __restrict__ Bqkv_h, __nv_bfloat16* __restrict__ Bqkv_l,
    const float* __restrict__ Wo, __nv_bfloat16* __restrict__ Bo_h, __nv_bfloat16* __restrict__ Bo_l,
    const float* __restrict__ W1, __nv_bfloat16* __restrict__ B1_h, __nv_bfloat16* __restrict__ B1_l,
    const float* __restrict__ W2, __nv_bfloat16* __restrict__ B2_h, __nv_bfloat16* __restrict__ B2_l) {
    __shared__ float t[32][33];
    int bid = blockIdx.x;
    const float* W;
    __nv_bfloat16 *Th, *Tl;
    int K, N, k0, n0, nout;
    if (bid < 4096) {
        int w = bid >> 10, lb = bid & 1023;
        K = DMODEL; N = DMODEL;
        k0 = (lb & 31) * 32; n0 = (lb >> 5) * 32;
        if (w < 3) {
            W = (w == 0) ? Wq : (w == 1) ? Wk : Wv;
            Th = Bqkv_h; Tl = Bqkv_l;
            nout = n0 + w * DMODEL;
        } else {
            W = Wo; Th = Bo_h; Tl = Bo_l; nout = n0;
        }
    } else if (bid < 6144) {
        int lb = bid - 4096;
        K = DMODEL; N = 2 * DMODEL;
        k0 = (lb & 31) * 32; n0 = (lb >> 5) * 32;
        W = W1; Th = B1_h; Tl = B1_l; nout = n0;
    } else {
        int lb = bid - 6144;
        K = 2 * DMODEL; N = DMODEL;
        k0 = (lb & 63) * 32; n0 = (lb >> 6) * 32;
        W = W2; Th = B2_h; Tl = B2_l; nout = n0;
    }
    int tx = threadIdx.x & 31, ty = threadIdx.x >> 5;
    #pragma unroll
    for (int i = 0; i < 4; ++i)
        t[ty + i * 8][tx] = W[(size_t)(k0 + ty + i * 8) * N + n0 + tx];
    __syncthreads();
    #pragma unroll
    for (int i = 0; i < 4; ++i) {
        int n = nout + ty + i * 8, k = k0 + tx;
        float x = t[tx][ty + i * 8];
        __nv_bfloat16 h = __float2bfloat16_rn(x);
        float lo = x - __bfloat162float(h);
        Th[(size_t)n * K + k] = h;
        Tl[(size_t)n * K + k] = __float2bfloat16_rn(lo);
    }
}

// ---------------- LayerNorm -> bf16 hi/lo ----------------------------
__global__ void __launch_bounds__(256) ln_kernel(const float* __restrict__ x,
                                                 const float* __restrict__ g,
                                                 const float* __restrict__ b,
                                                 __nv_bfloat16* __restrict__ outh,
                                                 __nv_bfloat16* __restrict__ outl) {
    int row = blockIdx.x;
    int tid = threadIdx.x;
    const float4* xr = (const float4*)(x + (size_t)row * DMODEL);
    float4 v = xr[tid];
    float s  = v.x + v.y + v.z + v.w;
    float ss = v.x * v.x + v.y * v.y + v.z * v.z + v.w * v.w;
    #pragma unroll
    for (int o = 16; o > 0; o >>= 1) {
        s  += __shfl_xor_sync(0xffffffffu, s,  o);
        ss += __shfl_xor_sync(0xffffffffu, ss, o);
    }
    __shared__ float sh[16];
    int w = tid >> 5;
    if ((tid & 31) == 0) { sh[w] = s; sh[8 + w] = ss; }
    __syncthreads();
    if (tid < 32) {
        float a  = (tid < 8) ? sh[tid]     : 0.0f;
        float a2 = (tid < 8) ? sh[8 + tid] : 0.0f;
        #pragma unroll
        for (int o = 4; o > 0; o >>= 1) {
            a  += __shfl_xor_sync(0xffffffffu, a,  o);
            a2 += __shfl_xor_sync(0xffffffffu, a2, o);
        }
        if (tid == 0) { sh[0] = a; sh[1] = a2; }
    }
    __syncthreads();
    float mean = sh[0] * (1.0f / DMODEL);
    float var  = sh[1] * (1.0f / DMODEL) - mean * mean;
    float rstd = rsqrtf(var + 1e-5f);
    float4 gg = ((const float4*)g)[tid];
    float4 bb = ((const float4*)b)[tid];
    float o0 = (v.x - mean) * rstd * gg.x + bb.x;
    float o1 = (v.y - mean) * rstd * gg.y + bb.y;
    float o2 = (v.z - mean) * rstd * gg.z + bb.z;
    float o3 = (v.w - mean) * rstd * gg.w + bb.w;
    uint2 h, l;
    split2(o0, o1, h.x, l.x);
    split2(o2, o3, h.y, l.y);
    ((uint2*)(outh + (size_t)row * DMODEL))[tid] = h;
    ((uint2*)(outl + (size_t)row * DMODEL))[tid] = l;
}

// ---------------- HMMA GEMM (r11 proven): 256 thr, 3-stage swizzled --
// OHALF: OSPLIT output stored as fp16 hi/lo (for attention inputs).
#define HG_A_L   8192
#define HG_B     16384
#define HG_B_L   8192
#define HG_STAGE 32768
#define HG_SMEM_BYTES (3 * HG_STAGE)

template <int GELU, int HAS_BIAS, int HAS_RES, int OSPLIT, int OHALF>
__global__ void __launch_bounds__(256, 2) hgemm_kernel(
    const __nv_bfloat16* __restrict__ Ah, const __nv_bfloat16* __restrict__ Al,
    const __nv_bfloat16* __restrict__ Bh, const __nv_bfloat16* __restrict__ Bl,
    const float* __restrict__ bias, const float* __restrict__ res,
    float* __restrict__ C, __nv_bfloat16* __restrict__ Ch,
    __nv_bfloat16* __restrict__ Cl, int M, int N, int K) {
    extern __shared__ __align__(16) char smem[];
    uint32_t uS = smem_u32(smem);

    int tid = threadIdx.x;
    int lane = tid & 31, wid = tid >> 5;
    int wm = wid >> 2, wn = wid & 3;
    int bm = blockIdx.y * 128, bn = blockIdx.x * 128;

    float acc[4][4][4];
    #pragma unroll
    for (int i = 0; i < 4; ++i)
        #pragma unroll
        for (int j = 0; j < 4; ++j)
            #pragma unroll
            for (int k = 0; k < 4; ++k) acc[i][j][k] = 0.0f;

    int q = lane >> 3, rr = lane & 7;
    int a_row = wm * 64 + (q & 1) * 8 + rr;
    int a_cb  = 16 * (q >> 1);
    int b_row = wn * 32 + (q >> 1) * 8 + rr;
    int b_cb  = 16 * (q & 1);

    int lr = tid >> 2, lck = (tid & 3) << 4;
    const int NC = K >> 5;

    auto load_chunk = [&](int c, int s) {
        uint32_t sb = uS + (uint32_t)s * HG_STAGE;
        int kc = c << 5;
        #pragma unroll
        for (int i = 0; i < 2; ++i) {
            int r = lr + i * 64;
            uint32_t d = sb + SWZ64((uint32_t)(r * 64 + lck));
            CP16(d, Ah + (size_t)(bm + r) * K + kc + (lck >> 1));
            CP16(d + HG_A_L, Al + (size_t)(bm + r) * K + kc + (lck >> 1));
        }
        #pragma unroll
        for (int i = 0; i < 2; ++i) {
            int r = lr + i * 64;
            uint32_t d = sb + HG_B + SWZ64((uint32_t)(r * 64 + lck));
            CP16(d, Bh + (size_t)(bn + r) * K + kc + (lck >> 1));
            CP16(d + HG_B_L, Bl + (size_t)(bn + r) * K + kc + (lck >> 1));
        }
        CP_COMMIT();
    };

    load_chunk(0, 0);
    if (NC > 1) load_chunk(1, 1);

    for (int c = 0; c < NC; ++c) {
        if (c + 2 < NC) { load_chunk(c + 2, (c + 2) % 3); CP_WAIT2(); }
        else if (c + 1 < NC) { CP_WAIT1(); }
        else { CP_WAIT0(); }
        __syncthreads();

        uint32_t sb = uS + (uint32_t)(c % 3) * HG_STAGE;
        #pragma unroll
        for (int ks = 0; ks < 2; ++ks) {
            uint32_t ahf[4][4], alf[4][4];
            #pragma unroll
            for (int mi = 0; mi < 4; ++mi) {
                uint32_t off = sb + SWZ64(
                    (uint32_t)((a_row + mi * 16) * 64 + a_cb + ks * 32));
                LDM_X4(ahf[mi][0], ahf[mi][1], ahf[mi][2], ahf[mi][3], off);
                LDM_X4(alf[mi][0], alf[mi][1], alf[mi][2], alf[mi][3], off + HG_A_L);
            }
            #pragma unroll
            for (int j2 = 0; j2 < 2; ++j2) {
                uint32_t bhf[2][2], blf[2][2];
                uint32_t off = sb + HG_B + SWZ64(
                    (uint32_t)((b_row + j2 * 16) * 64 + b_cb + ks * 32));
                LDM_X4(bhf[0][0], bhf[0][1], bhf[1][0], bhf[1][1], off);
                LDM_X4(blf[0][0], blf[0][1], blf[1][0], blf[1][1], off + HG_B_L);
                #pragma unroll
                for (int mi = 0; mi < 4; ++mi)
                    #pragma unroll
                    for (int nj = 0; nj < 2; ++nj) {
                        int ni = j2 * 2 + nj;
                        MMA16816(acc[mi][ni], ahf[mi], bhf[nj][0], bhf[nj][1]);
                        MMA16816(acc[mi][ni], alf[mi], bhf[nj][0], bhf[nj][1]);
                        MMA16816(acc[mi][ni], ahf[mi], blf[nj][0], blf[nj][1]);
                    }
            }
        }
        __syncthreads();
    }

    int gid = lane >> 2, tig = lane & 3;
    #pragma unroll
    for (int mi = 0; mi < 4; ++mi) {
        #pragma unroll
        for (int ni = 0; ni < 4; ++ni) {
            int row0 = bm + wm * 64 + mi * 16 + gid;
            int col  = bn + wn * 32 + ni * 8 + tig * 2;
            float c0 = acc[mi][ni][0], c1 = acc[mi][ni][1];
            float c2 = acc[mi][ni][2], c3 = acc[mi][ni][3];
            if (HAS_BIAS) {
                float b0 = bias[col], b1v = bias[col + 1];
                c0 += b0; c1 += b1v; c2 += b0; c3 += b1v;
            }
            if (GELU) {
                c0 = gelu_exact(c0); c1 = gelu_exact(c1);
                c2 = gelu_exact(c2); c3 = gelu_exact(c3);
            }
            if (HAS_RES) {
                float2 r0 = *(const float2*)&res[(size_t)row0 * N + col];
                float2 r1 = *(const float2*)&res[(size_t)(row0 + 8) * N + col];
                c0 += r0.x; c1 += r0.y; c2 += r1.x; c3 += r1.y;
            }
            if (OSPLIT) {
                uint32_t h0, l0, h1, l1;
                if (OHALF) {
                    split2h(c0, c1, h0, l0);
                    split2h(c2, c3, h1, l1);
                } else {
                    split2(c0, c1, h0, l0);
                    split2(c2, c3, h1, l1);
                }
                *(uint32_t*)&Ch[(size_t)row0 * N + col] = h0;
                *(uint32_t*)&Cl[(size_t)row0 * N + col] = l0;
                *(uint32_t*)&Ch[(size_t)(row0 + 8) * N + col] = h1;
                *(uint32_t*)&Cl[(size_t)(row0 + 8) * N + col] = l1;
            } else {
                float2 o0; o0.x = c0; o0.y = c1;
                float2 o1; o1.x = c2; o1.y = c3;
                *(float2*)&C[(size_t)row0 * N + col] = o0;
                *(float2*)&C[(size_t)(row0 + 8) * N + col] = o1;
            }
        }
    }
}

// ---------------- Tensor-core flash attention (fp16, 2-product) ------
// Q hi/lo in regs; K/V hi-only in smem (stage = Kh 8KB + Vh 8KB = 16KB,
// 2 stages = 32KB). S = QhKh + QlKh; PV = PhVh + PlVh.
#define AT_V     8192
#define AT_STAGE 16384
#define AT_SMEM  (2 * AT_STAGE)  // 32768

__global__ void __launch_bounds__(128, 3) attn_kernel(
    const __half* __restrict__ QKVh, const __half* __restrict__ QKVl,
    __nv_bfloat16* __restrict__ Oh, __nv_bfloat16* __restrict__ Ol) {
    extern __shared__ __align__(16) char smem[];
    uint32_t uS = smem_u32(smem);

    int qt = 31 - (int)blockIdx.x;   // heavy-first
    int bh = blockIdx.y;
    int b = bh >> 4, h = bh & 15;
    int tid = threadIdx.x, lane = tid & 31, wid = tid >> 5;
    int gid = lane >> 2, tig = lane & 3;
    int q = lane >> 3, rr = lane & 7;

    size_t rowbase = (size_t)b * SEQT;

    // K/V tile loader: 64 rows x 128B, SW128 swizzled within tile.
    auto ld_kv = [&](uint32_t dst, int trow, int cbase) {
        #pragma unroll
        for (int i = 0; i < 4; ++i) {
            int idx = tid + i * 128;
            int r = idx >> 3, c8 = (idx & 7) << 3;
            CP16(dst + SWZ128B((uint32_t)(r * 128 + c8 * 2)),
                 QKVh + (rowbase + trow + r) * (size_t)DM3 + cbase + h * HDIM + c8);
        }
    };

    // prologue: KV tile 0
    ld_kv(uS, 0, DMODEL);
    ld_kv(uS + AT_V, 0, 2 * DMODEL);
    CP_COMMIT();

    // Q fragments hi/lo, loaded once from gmem (A-frag mapping).
    uint32_t qh[4][4], ql[4][4];
    {
        int row0 = qt * 64 + wid * 16 + gid;
        size_t base0 = (rowbase + row0) * (size_t)DM3 + h * HDIM;
        size_t base8 = base0 + 8 * (size_t)DM3;
        #pragma unroll
        for (int ks = 0; ks < 4; ++ks) {
            int c0 = ks * 16 + 2 * tig;
            qh[ks][0] = *(const uint32_t*)&QKVh[base0 + c0];
            qh[ks][1] = *(const uint32_t*)&QKVh[base8 + c0];
            qh[ks][2] = *(const uint32_t*)&QKVh[base0 + c0 + 8];
            qh[ks][3] = *(const uint32_t*)&QKVh[base8 + c0 + 8];
            ql[ks][0] = *(const uint32_t*)&QKVl[base0 + c0];
            ql[ks][1] = *(const uint32_t*)&QKVl[base8 + c0];
            ql[ks][2] = *(const uint32_t*)&QKVl[base0 + c0 + 8];
            ql[ks][3] = *(const uint32_t*)&QKVl[base8 + c0 + 8];
        }
    }

    float oacc[8][4];
    #pragma unroll
    for (int i = 0; i < 8; ++i)
        #pragma unroll
        for (int j = 0; j < 4; ++j) oacc[i][j] = 0.0f;
    float m0 = -1e30f, m1 = -1e30f, l0 = 0.0f, l1 = 0.0f;

    int b_rsel = (q >> 1) * 8 + rr;  // + j2*16
    int b_csel = (q & 1) * 8;        // + ks*16
    int v_rsel = (q & 1) * 8 + rr;   // + ks*16
    int v_csel = (q >> 1) * 8;       // + j2*16

    for (int kt = 0; kt <= qt; ++kt) {
        uint32_t st = uS + (uint32_t)(kt & 1) * AT_STAGE;
        if (kt < qt) {
            uint32_t s2 = uS + (uint32_t)((kt + 1) & 1) * AT_STAGE;
            ld_kv(s2, (kt + 1) * 64, DMODEL);
            ld_kv(s2 + AT_V, (kt + 1) * 64, 2 * DMODEL);
            CP_COMMIT();
            CP_WAIT1();
        } else {
            CP_WAIT0();
        }
        __syncthreads();

        // ---- S = Q K^T (2-product: Qh.Kh + Ql.Kh) ----
        float sc[8][4];
        #pragma unroll
        for (int i = 0; i < 8; ++i)
            #pragma unroll
            for (int j = 0; j < 4; ++j) sc[i][j] = 0.0f;

        #pragma unroll
        for (int ks = 0; ks < 4; ++ks) {
            #pragma unroll
            for (int j2 = 0; j2 < 4; ++j2) {
                uint32_t kh0, kh1, kh2, kh3;
                uint32_t boff = st + SWZ128B(
                    (uint32_t)((j2 * 16 + b_rsel) * 128 + (b_csel + ks * 16) * 2));
                LDM_X4(kh0, kh1, kh2, kh3, boff);
                MMAH16(sc[2 * j2],     qh[ks], kh0, kh1);
                MMAH16(sc[2 * j2],     ql[ks], kh0, kh1);
                MMAH16(sc[2 * j2 + 1], qh[ks], kh2, kh3);
                MMAH16(sc[2 * j2 + 1], ql[ks], kh2, kh3);
            }
        }

        // scale + causal mask
        #pragma unroll
        for (int ni = 0; ni < 8; ++ni) {
            sc[ni][0] *= 0.125f; sc[ni][1] *= 0.125f;
            sc[ni][2] *= 0.125f; sc[ni][3] *= 0.125f;
        }
        if (kt == qt) {
            int r0 = wid * 16 + gid, r1 = r0 + 8;
            #pragma unroll
            for (int ni = 0; ni < 8; ++ni) {
                int c0 = ni * 8 + tig * 2, c1 = c0 + 1;
                if (c0 > r0) sc[ni][0] = -1e30f;
                if (c1 > r0) sc[ni][1] = -1e30f;
                if (c0 > r1) sc[ni][2] = -1e30f;
                if (c1 > r1) sc[ni][3] = -1e30f;
            }
        }

        // ---- online softmax in registers ----
        float t0 = -1e30f, t1 = -1e30f;
        #pragma unroll
        for (int ni = 0; ni < 8; ++ni) {
            t0 = fmaxf(t0, fmaxf(sc[ni][0], sc[ni][1]));
            t1 = fmaxf(t1, fmaxf(sc[ni][2], sc[ni][3]));
        }
        t0 = fmaxf(t0, __shfl_xor_sync(0xffffffffu, t0, 1));
        t0 = fmaxf(t0, __shfl_xor_sync(0xffffffffu, t0, 2));
        t1 = fmaxf(t1, __shfl_xor_sync(0xffffffffu, t1, 1));
        t1 = fmaxf(t1, __shfl_xor_sync(0xffffffffu, t1, 2));
        float mn0 = fmaxf(m0, t0), mn1 = fmaxf(m1, t1);
        float al0 = __expf(m0 - mn0), al1 = __expf(m1 - mn1);
        m0 = mn0; m1 = mn1;

        float sum0 = 0.0f, sum1 = 0.0f;
        uint32_t pah[4][4], pal[4][4];
        #pragma unroll
        for (int kp = 0; kp < 4; ++kp) {
            float p00 = __expf(sc[2 * kp][0] - mn0);
            float p01 = __expf(sc[2 * kp][1] - mn0);
            float p02 = __expf(sc[2 * kp][2] - mn1);
            float p03 = __expf(sc[2 * kp][3] - mn1);
            float p10 = __expf(sc[2 * kp + 1][0] - mn0);
            float p11 = __expf(sc[2 * kp + 1][1] - mn0);
            float p12 = __expf(sc[2 * kp + 1][2] - mn1);
            float p13 = __expf(sc[2 * kp + 1][3] - mn1);
            sum0 += p00 + p01 + p10 + p11;
            sum1 += p02 + p03 + p12 + p13;
            split2h(p00, p01, pah[kp][0], pal[kp][0]);
            split2h(p02, p03, pah[kp][1], pal[kp][1]);
            split2h(p10, p11, pah[kp][2], pal[kp][2]);
            split2h(p12, p13, pah[kp][3], pal[kp][3]);
        }
        sum0 += __shfl_xor_sync(0xffffffffu, sum0, 1);
        sum0 += __shfl_xor_sync(0xffffffffu, sum0, 2);
        sum1 += __shfl_xor_sync(0xffffffffu, sum1, 1);
        sum1 += __shfl_xor_sync(0xffffffffu, sum1, 2);
        l0 = l0 * al0 + sum0;
        l1 = l1 * al1 + sum1;
        #pragma unroll
        for (int ni = 0; ni < 8; ++ni) {
            oacc[ni][0] *= al0; oacc[ni][1] *= al0;
            oacc[ni][2] *= al1; oacc[ni][3] *= al1;
        }

        // ---- O += P V (2-product: Ph.Vh + Pl.Vh; V via trans-ldmatrix) ----
        #pragma unroll
        for (int ks = 0; ks < 4; ++ks) {
            #pragma unroll
            for (int j2 = 0; j2 < 4; ++j2) {
                uint32_t vh0, vh1, vh2, vh3;
                uint32_t voff = st + AT_V + SWZ128B(
                    (uint32_t)((ks * 16 + v_rsel) * 128 + (v_csel + j2 * 16) * 2));
                LDM_X4T(vh0, vh1, vh2, vh3, voff);
                MMAH16(oacc[2 * j2],     pah[ks], vh0, vh1);
                MMAH16(oacc[2 * j2],     pal[ks], vh0, vh1);
                MMAH16(oacc[2 * j2 + 1], pah[ks], vh2, vh3);
                MMAH16(oacc[2 * j2 + 1], pal[ks], vh2, vh3);
            }
        }
        __syncthreads();
    }

    // ---- output: ctx bf16 hi/lo ----
    float inv0 = 1.0f / l0, inv1 = 1.0f / l1;
    int grow = qt * 64 + wid * 16 + gid;
    #pragma unroll
    for (int ni = 0; ni < 8; ++ni) {
        size_t i0 = (rowbase + grow) * (size_t)DMODEL + h * HDIM + ni * 8 + tig * 2;
        size_t i1 = i0 + 8 * (size_t)DMODEL;
        uint32_t hh, ll;
        split2(oacc[ni][0] * inv0, oacc[ni][1] * inv0, hh, ll);
        *(uint32_t*)&Oh[i0] = hh;
        *(uint32_t*)&Ol[i0] = ll;
        split2(oacc[ni][2] * inv1, oacc[ni][3] * inv1, hh, ll);
        *(uint32_t*)&Oh[i1] = hh;
        *(uint32_t*)&Ol[i1] = ll;
    }
}

// ---------------- launch -------------------------------------------
static void* sym_addr(const void* sym) {
    void* p = nullptr;
    cudaGetSymbolAddress(&p, sym);
    return p;
}

extern "C" void kernel_launch(void* const* d_in, const int* in_sizes, int n_in,
                              void* d_out, int out_size) {
    const float* x     = (const float*)d_in[0];
    const float* ln1_g = (const float*)d_in[1];
    const float* ln1_b = (const float*)d_in[2];
    const float* Wq    = (const float*)d_in[3];
    const float* Wk    = (const float*)d_in[4];
    const float* Wv    = (const float*)d_in[5];
    const float* Wo    = (const float*)d_in[6];
    const float* ln2_g = (const float*)d_in[7];
    const float* ln2_b = (const float*)d_in[8];
    const float* W1    = (const float*)d_in[9];
    const float* b1    = (const float*)d_in[10];
    const float* W2    = (const float*)d_in[11];
    const float* b2    = (const float*)d_in[12];
    float* out = (float*)d_out;

    float* x2 = (float*)sym_addr(g_x2);
    __nv_bfloat16* lnh   = (__nv_bfloat16*)sym_addr(g_lnh);
    __nv_bfloat16* lnl   = (__nv_bfloat16*)sym_addr(g_lnl);
    __half* qkvh         = (__half*)sym_addr(g_qkvh);
    __half* qkvl         = (__half*)sym_addr(g_qkvl);
    __nv_bfloat16* ctxh  = (__nv_bfloat16*)sym_addr(g_ctxh);
    __nv_bfloat16* ctxl  = (__nv_bfloat16*)sym_addr(g_ctxl);
    __nv_bfloat16* ffh   = (__nv_bfloat16*)sym_addr(g_ffh);
    __nv_bfloat16* ffl   = (__nv_bfloat16*)sym_addr(g_ffl);

    __nv_bfloat16* Bqkv_h = (__nv_bfloat16*)sym_addr(g_Bqkv_h);
    __nv_bfloat16* Bqkv_l = (__nv_bfloat16*)sym_addr(g_Bqkv_l);
    __nv_bfloat16* Bo_h = (__nv_bfloat16*)sym_addr(g_Bo_h);
    __nv_bfloat16* Bo_l = (__nv_bfloat16*)sym_addr(g_Bo_l);
    __nv_bfloat16* B1_h = (__nv_bfloat16*)sym_addr(g_B1_h);
    __nv_bfloat16* B1_l = (__nv_bfloat16*)sym_addr(g_B1_l);
    __nv_bfloat16* B2_h = (__nv_bfloat16*)sym_addr(g_B2_h);
    __nv_bfloat16* B2_l = (__nv_bfloat16*)sym_addr(g_B2_l);

    cudaFuncSetAttribute(hgemm_kernel<0, 0, 0, 1, 1>,
                         cudaFuncAttributeMaxDynamicSharedMemorySize, HG_SMEM_BYTES);
    cudaFuncSetAttribute(hgemm_kernel<0, 0, 1, 0, 0>,
                         cudaFuncAttributeMaxDynamicSharedMemorySize, HG_SMEM_BYTES);
    cudaFuncSetAttribute(hgemm_kernel<1, 1, 0, 1, 0>,
                         cudaFuncAttributeMaxDynamicSharedMemorySize, HG_SMEM_BYTES);
    cudaFuncSetAttribute(hgemm_kernel<0, 1, 1, 0, 0>,
                         cudaFuncAttributeMaxDynamicSharedMemorySize, HG_SMEM_BYTES);
    cudaFuncSetAttribute(attn_kernel,
                         cudaFuncAttributeMaxDynamicSharedMemorySize, AT_SMEM);

    dim3 blk128(128), blk256(256);
    dim3 gqkv(DM3 / 128, MROWS / 128);         // (24, 32)
    dim3 g1k(DMODEL / 128, MROWS / 128);       // (8, 32)
    dim3 g2k(2 * DMODEL / 128, MROWS / 128);   // (16, 32)

    // 0: weight prep
    wsplit_all_kernel<<<8192, blk256>>>(Wq, Wk, Wv, Bqkv_h, Bqkv_l,
                                        Wo, Bo_h, Bo_l,
                                        W1, B1_h, B1_l, W2, B2_h, B2_l);
    // 1: LN1
    ln_kernel<<<MROWS, blk256>>>(x, ln1_g, ln1_b, lnh, lnl);
    // 2: merged QKV projection -> fp16 hi/lo
    hgemm_kernel<0, 0, 0, 1, 1><<<gqkv, blk256, HG_SMEM_BYTES>>>(
        lnh, lnl, Bqkv_h, Bqkv_l, nullptr, nullptr, nullptr,
        (__nv_bfloat16*)qkvh, (__nv_bfloat16*)qkvl, MROWS, DM3, DMODEL);
    // 3: attention (fp16 2-product, Q-in-regs, hi-only K/V)
    attn_kernel<<<dim3(32, 32), blk128, AT_SMEM>>>(qkvh, qkvl, ctxh, ctxl);
    // 4: output projection + residual(x)
    hgemm_kernel<0, 0, 1, 0, 0><<<g1k, blk256, HG_SMEM_BYTES>>>(
        ctxh, ctxl, Bo_h, Bo_l, nullptr, x, x2, nullptr, nullptr,
        MROWS, DMODEL, DMODEL);
    // 5: LN2
    ln_kernel<<<MROWS, blk256>>>(x2, ln2_g, ln2_b, lnh, lnl);
    // 6: FFN up + bias + GELU
    hgemm_kernel<1, 1, 0, 1, 0><<<g2k, blk256, HG_SMEM_BYTES>>>(
        lnh, lnl, B1_h, B1_l, b1, nullptr, nullptr, ffh, ffl,
        MROWS, 2 * DMODEL, DMODEL);
    // 7: FFN down + bias + residual(x2) -> out
    hgemm_kernel<0, 1, 1, 0, 0><<<g1k, blk256, HG_SMEM_BYTES>>>(
        ffh, ffl, B2_h, B2_l, b2, x2, out, nullptr, nullptr,
        MROWS, DMODEL, 2 * DMODEL);
}

// round 15
// speedup vs baseline: 1.4614x; 1.2984x over previous
#include <cuda_runtime.h>
#include <cuda_bf16.h>
#include <cuda_fp16.h>
#include <math.h>
#include <stdint.h>

#define DMODEL 1024
#define SEQT   2048
#define BATCH  2
#define MROWS  4096   // BATCH * SEQT
#define NHEAD  16
#define HDIM   64
#define DM3    (3 * DMODEL)

// ---------------- scratch (static device allocations) ----------------
__device__ float g_x2 [MROWS * DMODEL];
__device__ __half g_lnh [MROWS * DMODEL], g_lnl [MROWS * DMODEL];
__device__ __half g_qkvh[MROWS * DM3],    g_qkvl[MROWS * DM3];
__device__ __half g_ctxh[MROWS * DMODEL], g_ctxl[MROWS * DMODEL];
__device__ __half g_ffh [MROWS * 2 * DMODEL], g_ffl [MROWS * 2 * DMODEL];

// transposed weights: [N][K] fp16 hi-only
__device__ __half g_Bqkv[DM3 * DMODEL];
__device__ __half g_Bo[DMODEL * DMODEL];
__device__ __half g_B1[2 * DMODEL * DMODEL];
__device__ __half g_B2[2 * DMODEL * DMODEL];

// ---------------- helpers --------------------------------------------
__device__ __forceinline__ uint32_t smem_u32(const void* p) {
    uint32_t a;
    asm("{ .reg .u64 t; cvta.to.shared.u64 t, %1; cvt.u32.u64 %0, t; }"
        : "=r"(a) : "l"(p));
    return a;
}
__device__ __forceinline__ float gelu_exact(float x) {
    return 0.5f * x * (1.0f + erff(x * 0.70710678118654752f));
}
// fp16 hi/lo split
__device__ __forceinline__ void split2h(float x, float y, uint32_t& h, uint32_t& l) {
    __half2 hh = __float22half2_rn(make_float2(x, y));
    float2 f = __half22float2(hh);
    __half2 ll = __float22half2_rn(make_float2(x - f.x, y - f.y));
    h = *(uint32_t*)&hh;
    l = *(uint32_t*)&ll;
}

#define LDM_X4(r0, r1, r2, r3, addr) \
    asm volatile("ldmatrix.sync.aligned.m8n8.x4.shared.b16 {%0,%1,%2,%3}, [%4];" \
        : "=r"(r0), "=r"(r1), "=r"(r2), "=r"(r3) : "r"(addr))
#define LDM_X4T(r0, r1, r2, r3, addr) \
    asm volatile("ldmatrix.sync.aligned.m8n8.x4.trans.shared.b16 {%0,%1,%2,%3}, [%4];" \
        : "=r"(r0), "=r"(r1), "=r"(r2), "=r"(r3) : "r"(addr))

// fp16 MMA
#define MMAH16(d, a, b0, b1) \
    asm volatile("mma.sync.aligned.m16n8k16.row.col.f32.f16.f16.f32 " \
        "{%0,%1,%2,%3}, {%4,%5,%6,%7}, {%8,%9}, {%0,%1,%2,%3};" \
        : "+f"((d)[0]), "+f"((d)[1]), "+f"((d)[2]), "+f"((d)[3]) \
        : "r"((a)[0]), "r"((a)[1]), "r"((a)[2]), "r"((a)[3]), \
          "r"(b0), "r"(b1))

#define CP16(dst, src) \
    asm volatile("cp.async.cg.shared.global [%0], [%1], 16;" \
        :: "r"(dst), "l"(src))
#define CP_COMMIT() asm volatile("cp.async.commit_group;")
#define CP_WAIT2()  asm volatile("cp.async.wait_group 2;")
#define CP_WAIT1()  asm volatile("cp.async.wait_group 1;")
#define CP_WAIT0()  asm volatile("cp.async.wait_group 0;")

// 64B-row tile swizzle for GEMM smem.
#define SWZ64(off) ((off) ^ ((((off) >> 7) & 3u) << 4))
// 128B-row tile swizzle (standard SW128) for attention K/V smem.
#define SWZ128B(off) ((off) ^ (((off) >> 3) & 0x70u))

// ---------------- weight prep: transpose -> fp16 hi-only -------------
__global__ void __launch_bounds__(256) wsplit_all_kernel(
    const float* __restrict__ Wq, const float* __restrict__ Wk,
    const float* __restrict__ Wv, __half* __restrict__ Bqkv,
    const float* __restrict__ Wo, __half* __restrict__ Bo,
    const float* __restrict__ W1, __half* __restrict__ B1,
    const float* __restrict__ W2, __half* __restrict__ B2) {
    __shared__ float t[32][33];
    int bid = blockIdx.x;
    const float* W;
    __half* Th;
    int K, N, k0, n0, nout;
    if (bid < 4096) {
        int w = bid >> 10, lb = bid & 1023;
        K = DMODEL; N = DMODEL;
        k0 = (lb & 31) * 32; n0 = (lb >> 5) * 32;
        if (w < 3) {
            W = (w == 0) ? Wq : (w == 1) ? Wk : Wv;
            Th = Bqkv;
            nout = n0 + w * DMODEL;
        } else {
            W = Wo; Th = Bo; nout = n0;
        }
    } else if (bid < 6144) {
        int lb = bid - 4096;
        K = DMODEL; N = 2 * DMODEL;
        k0 = (lb & 31) * 32; n0 = (lb >> 5) * 32;
        W = W1; Th = B1; nout = n0;
    } else {
        int lb = bid - 6144;
        K = 2 * DMODEL; N = DMODEL;
        k0 = (lb & 63) * 32; n0 = (lb >> 6) * 32;
        W = W2; Th = B2; nout = n0;
    }
    int tx = threadIdx.x & 31, ty = threadIdx.x >> 5;
    #pragma unroll
    for (int i = 0; i < 4; ++i)
        t[ty + i * 8][tx] = W[(size_t)(k0 + ty + i * 8) * N + n0 + tx];
    __syncthreads();
    #pragma unroll
    for (int i = 0; i < 4; ++i) {
        int n = nout + ty + i * 8, k = k0 + tx;
        Th[(size_t)n * K + k] = __float2half_rn(t[tx][ty + i * 8]);
    }
}

// ---------------- LayerNorm -> fp16 hi/lo ----------------------------
__global__ void __launch_bounds__(256) ln_kernel(const float* __restrict__ x,
                                                 const float* __restrict__ g,
                                                 const float* __restrict__ b,
                                                 __half* __restrict__ outh,
                                                 __half* __restrict__ outl) {
    int row = blockIdx.x;
    int tid = threadIdx.x;
    const float4* xr = (const float4*)(x + (size_t)row * DMODEL);
    float4 v = xr[tid];
    float s  = v.x + v.y + v.z + v.w;
    float ss = v.x * v.x + v.y * v.y + v.z * v.z + v.w * v.w;
    #pragma unroll
    for (int o = 16; o > 0; o >>= 1) {
        s  += __shfl_xor_sync(0xffffffffu, s,  o);
        ss += __shfl_xor_sync(0xffffffffu, ss, o);
    }
    __shared__ float sh[16];
    int w = tid >> 5;
    if ((tid & 31) == 0) { sh[w] = s; sh[8 + w] = ss; }
    __syncthreads();
    if (tid < 32) {
        float a  = (tid < 8) ? sh[tid]     : 0.0f;
        float a2 = (tid < 8) ? sh[8 + tid] : 0.0f;
        #pragma unroll
        for (int o = 4; o > 0; o >>= 1) {
            a  += __shfl_xor_sync(0xffffffffu, a,  o);
            a2 += __shfl_xor_sync(0xffffffffu, a2, o);
        }
        if (tid == 0) { sh[0] = a; sh[1] = a2; }
    }
    __syncthreads();
    float mean = sh[0] * (1.0f / DMODEL);
    float var  = sh[1] * (1.0f / DMODEL) - mean * mean;
    float rstd = rsqrtf(var + 1e-5f);
    float4 gg = ((const float4*)g)[tid];
    float4 bb = ((const float4*)b)[tid];
    float o0 = (v.x - mean) * rstd * gg.x + bb.x;
    float o1 = (v.y - mean) * rstd * gg.y + bb.y;
    float o2 = (v.z - mean) * rstd * gg.z + bb.z;
    float o3 = (v.w - mean) * rstd * gg.w + bb.w;
    uint2 h, l;
    split2h(o0, o1, h.x, l.x);
    split2h(o2, o3, h.y, l.y);
    ((uint2*)(outh + (size_t)row * DMODEL))[tid] = h;
    ((uint2*)(outl + (size_t)row * DMODEL))[tid] = l;
}

// ---------------- fp16 2-product GEMM: 256 thr, 3-stage swizzled -----
// C = A @ W; A fp16 hi/lo [M][K]; B = W^T fp16 hi-only [N][K].
// Per (mi,nj): AhBh + AlBh (2 MMAs). Stage = Ah 8K + Al 8K + Bh 8K.
#define HG_A_L   8192
#define HG_B     16384
#define HG_STAGE 24576
#define HG_SMEM_BYTES (3 * HG_STAGE)

template <int GELU, int HAS_BIAS, int HAS_RES, int OSPLIT>
__global__ void __launch_bounds__(256, 2) hgemm_kernel(
    const __half* __restrict__ Ah, const __half* __restrict__ Al,
    const __half* __restrict__ Bh,
    const float* __restrict__ bias, const float* __restrict__ res,
    float* __restrict__ C, __half* __restrict__ Ch,
    __half* __restrict__ Cl, int M, int N, int K) {
    extern __shared__ __align__(16) char smem[];
    uint32_t uS = smem_u32(smem);

    int tid = threadIdx.x;
    int lane = tid & 31, wid = tid >> 5;
    int wm = wid >> 2, wn = wid & 3;
    int bm = blockIdx.y * 128, bn = blockIdx.x * 128;

    float acc[4][4][4];
    #pragma unroll
    for (int i = 0; i < 4; ++i)
        #pragma unroll
        for (int j = 0; j < 4; ++j)
            #pragma unroll
            for (int k = 0; k < 4; ++k) acc[i][j][k] = 0.0f;

    int q = lane >> 3, rr = lane & 7;
    int a_row = wm * 64 + (q & 1) * 8 + rr;
    int a_cb  = 16 * (q >> 1);
    int b_row = wn * 32 + (q >> 1) * 8 + rr;
    int b_cb  = 16 * (q & 1);

    int lr = tid >> 2, lck = (tid & 3) << 4;
    const int NC = K >> 5;

    auto load_chunk = [&](int c, int s) {
        uint32_t sb = uS + (uint32_t)s * HG_STAGE;
        int kc = c << 5;
        #pragma unroll
        for (int i = 0; i < 2; ++i) {
            int r = lr + i * 64;
            uint32_t d = sb + SWZ64((uint32_t)(r * 64 + lck));
            CP16(d, Ah + (size_t)(bm + r) * K + kc + (lck >> 1));
            CP16(d + HG_A_L, Al + (size_t)(bm + r) * K + kc + (lck >> 1));
        }
        #pragma unroll
        for (int i = 0; i < 2; ++i) {
            int r = lr + i * 64;
            uint32_t d = sb + HG_B + SWZ64((uint32_t)(r * 64 + lck));
            CP16(d, Bh + (size_t)(bn + r) * K + kc + (lck >> 1));
        }
        CP_COMMIT();
    };

    load_chunk(0, 0);
    if (NC > 1) load_chunk(1, 1);

    for (int c = 0; c < NC; ++c) {
        if (c + 2 < NC) { load_chunk(c + 2, (c + 2) % 3); CP_WAIT2(); }
        else if (c + 1 < NC) { CP_WAIT1(); }
        else { CP_WAIT0(); }
        __syncthreads();

        uint32_t sb = uS + (uint32_t)(c % 3) * HG_STAGE;
        #pragma unroll
        for (int ks = 0; ks < 2; ++ks) {
            uint32_t ahf[4][4], alf[4][4];
            #pragma unroll
            for (int mi = 0; mi < 4; ++mi) {
                uint32_t off = sb + SWZ64(
                    (uint32_t)((a_row + mi * 16) * 64 + a_cb + ks * 32));
                LDM_X4(ahf[mi][0], ahf[mi][1], ahf[mi][2], ahf[mi][3], off);
                LDM_X4(alf[mi][0], alf[mi][1], alf[mi][2], alf[mi][3], off + HG_A_L);
            }
            #pragma unroll
            for (int j2 = 0; j2 < 2; ++j2) {
                uint32_t bhf[2][2];
                uint32_t off = sb + HG_B + SWZ64(
                    (uint32_t)((b_row + j2 * 16) * 64 + b_cb + ks * 32));
                LDM_X4(bhf[0][0], bhf[0][1], bhf[1][0], bhf[1][1], off);
                #pragma unroll
                for (int mi = 0; mi < 4; ++mi)
                    #pragma unroll
                    for (int nj = 0; nj < 2; ++nj) {
                        int ni = j2 * 2 + nj;
                        MMAH16(acc[mi][ni], ahf[mi], bhf[nj][0], bhf[nj][1]);
                        MMAH16(acc[mi][ni], alf[mi], bhf[nj][0], bhf[nj][1]);
                    }
            }
        }
        __syncthreads();
    }

    int gid = lane >> 2, tig = lane & 3;
    #pragma unroll
    for (int mi = 0; mi < 4; ++mi) {
        #pragma unroll
        for (int ni = 0; ni < 4; ++ni) {
            int row0 = bm + wm * 64 + mi * 16 + gid;
            int col  = bn + wn * 32 + ni * 8 + tig * 2;
            float c0 = acc[mi][ni][0], c1 = acc[mi][ni][1];
            float c2 = acc[mi][ni][2], c3 = acc[mi][ni][3];
            if (HAS_BIAS) {
                float b0 = bias[col], b1v = bias[col + 1];
                c0 += b0; c1 += b1v; c2 += b0; c3 += b1v;
            }
            if (GELU) {
                c0 = gelu_exact(c0); c1 = gelu_exact(c1);
                c2 = gelu_exact(c2); c3 = gelu_exact(c3);
            }
            if (HAS_RES) {
                float2 r0 = *(const float2*)&res[(size_t)row0 * N + col];
                float2 r1 = *(const float2*)&res[(size_t)(row0 + 8) * N + col];
                c0 += r0.x; c1 += r0.y; c2 += r1.x; c3 += r1.y;
            }
            if (OSPLIT) {
                uint32_t h0, l0, h1, l1;
                split2h(c0, c1, h0, l0);
                split2h(c2, c3, h1, l1);
                *(uint32_t*)&Ch[(size_t)row0 * N + col] = h0;
                *(uint32_t*)&Cl[(size_t)row0 * N + col] = l0;
                *(uint32_t*)&Ch[(size_t)(row0 + 8) * N + col] = h1;
                *(uint32_t*)&Cl[(size_t)(row0 + 8) * N + col] = l1;
            } else {
                float2 o0; o0.x = c0; o0.y = c1;
                float2 o1; o1.x = c2; o1.y = c3;
                *(float2*)&C[(size_t)row0 * N + col] = o0;
                *(float2*)&C[(size_t)(row0 + 8) * N + col] = o1;
            }
        }
    }
}

// ---------------- Tensor-core flash attention (fp16, 2-product) ------
// Q hi/lo in regs; K/V hi-only in smem (stage = Kh 8KB + Vh 8KB = 16KB,
// 2 stages = 32KB). S = QhKh + QlKh; PV = PhVh + PlVh.
#define AT_V     8192
#define AT_STAGE 16384
#define AT_SMEM  (2 * AT_STAGE)  // 32768

__global__ void __launch_bounds__(128, 3) attn_kernel(
    const __half* __restrict__ QKVh, const __half* __restrict__ QKVl,
    __half* __restrict__ Oh, __half* __restrict__ Ol) {
    extern __shared__ __align__(16) char smem[];
    uint32_t uS = smem_u32(smem);

    int qt = 31 - (int)blockIdx.x;   // heavy-first
    int bh = blockIdx.y;
    int b = bh >> 4, h = bh & 15;
    int tid = threadIdx.x, lane = tid & 31, wid = tid >> 5;
    int gid = lane >> 2, tig = lane & 3;
    int q = lane >> 3, rr = lane & 7;

    size_t rowbase = (size_t)b * SEQT;

    auto ld_kv = [&](uint32_t dst, int trow, int cbase) {
        #pragma unroll
        for (int i = 0; i < 4; ++i) {
            int idx = tid + i * 128;
            int r = idx >> 3, c8 = (idx & 7) << 3;
            CP16(dst + SWZ128B((uint32_t)(r * 128 + c8 * 2)),
                 QKVh + (rowbase + trow + r) * (size_t)DM3 + cbase + h * HDIM + c8);
        }
    };

    ld_kv(uS, 0, DMODEL);
    ld_kv(uS + AT_V, 0, 2 * DMODEL);
    CP_COMMIT();

    uint32_t qh[4][4], ql[4][4];
    {
        int row0 = qt * 64 + wid * 16 + gid;
        size_t base0 = (rowbase + row0) * (size_t)DM3 + h * HDIM;
        size_t base8 = base0 + 8 * (size_t)DM3;
        #pragma unroll
        for (int ks = 0; ks < 4; ++ks) {
            int c0 = ks * 16 + 2 * tig;
            qh[ks][0] = *(const uint32_t*)&QKVh[base0 + c0];
            qh[ks][1] = *(const uint32_t*)&QKVh[base8 + c0];
            qh[ks][2] = *(const uint32_t*)&QKVh[base0 + c0 + 8];
            qh[ks][3] = *(const uint32_t*)&QKVh[base8 + c0 + 8];
            ql[ks][0] = *(const uint32_t*)&QKVl[base0 + c0];
            ql[ks][1] = *(const uint32_t*)&QKVl[base8 + c0];
            ql[ks][2] = *(const uint32_t*)&QKVl[base0 + c0 + 8];
            ql[ks][3] = *(const uint32_t*)&QKVl[base8 + c0 + 8];
        }
    }

    float oacc[8][4];
    #pragma unroll
    for (int i = 0; i < 8; ++i)
        #pragma unroll
        for (int j = 0; j < 4; ++j) oacc[i][j] = 0.0f;
    float m0 = -1e30f, m1 = -1e30f, l0 = 0.0f, l1 = 0.0f;

    int b_rsel = (q >> 1) * 8 + rr;
    int b_csel = (q & 1) * 8;
    int v_rsel = (q & 1) * 8 + rr;
    int v_csel = (q >> 1) * 8;

    for (int kt = 0; kt <= qt; ++kt) {
        uint32_t st = uS + (uint32_t)(kt & 1) * AT_STAGE;
        if (kt < qt) {
            uint32_t s2 = uS + (uint32_t)((kt + 1) & 1) * AT_STAGE;
            ld_kv(s2, (kt + 1) * 64, DMODEL);
            ld_kv(s2 + AT_V, (kt + 1) * 64, 2 * DMODEL);
            CP_COMMIT();
            CP_WAIT1();
        } else {
            CP_WAIT0();
        }
        __syncthreads();

        float sc[8][4];
        #pragma unroll
        for (int i = 0; i < 8; ++i)
            #pragma unroll
            for (int j = 0; j < 4; ++j) sc[i][j] = 0.0f;

        #pragma unroll
        for (int ks = 0; ks < 4; ++ks) {
            #pragma unroll
            for (int j2 = 0; j2 < 4; ++j2) {
                uint32_t kh0, kh1, kh2, kh3;
                uint32_t boff = st + SWZ128B(
                    (uint32_t)((j2 * 16 + b_rsel) * 128 + (b_csel + ks * 16) * 2));
                LDM_X4(kh0, kh1, kh2, kh3, boff);
                MMAH16(sc[2 * j2],     qh[ks], kh0, kh1);
                MMAH16(sc[2 * j2],     ql[ks], kh0, kh1);
                MMAH16(sc[2 * j2 + 1], qh[ks], kh2, kh3);
                MMAH16(sc[2 * j2 + 1], ql[ks], kh2, kh3);
            }
        }

        #pragma unroll
        for (int ni = 0; ni < 8; ++ni) {
            sc[ni][0] *= 0.125f; sc[ni][1] *= 0.125f;
            sc[ni][2] *= 0.125f; sc[ni][3] *= 0.125f;
        }
        if (kt == qt) {
            int r0 = wid * 16 + gid, r1 = r0 + 8;
            #pragma unroll
            for (int ni = 0; ni < 8; ++ni) {
                int c0 = ni * 8 + tig * 2, c1 = c0 + 1;
                if (c0 > r0) sc[ni][0] = -1e30f;
                if (c1 > r0) sc[ni][1] = -1e30f;
                if (c0 > r1) sc[ni][2] = -1e30f;
                if (c1 > r1) sc[ni][3] = -1e30f;
            }
        }

        float t0 = -1e30f, t1 = -1e30f;
        #pragma unroll
        for (int ni = 0; ni < 8; ++ni) {
            t0 = fmaxf(t0, fmaxf(sc[ni][0], sc[ni][1]));
            t1 = fmaxf(t1, fmaxf(sc[ni][2], sc[ni][3]));
        }
        t0 = fmaxf(t0, __shfl_xor_sync(0xffffffffu, t0, 1));
        t0 = fmaxf(t0, __shfl_xor_sync(0xffffffffu, t0, 2));
        t1 = fmaxf(t1, __shfl_xor_sync(0xffffffffu, t1, 1));
        t1 = fmaxf(t1, __shfl_xor_sync(0xffffffffu, t1, 2));
        float mn0 = fmaxf(m0, t0), mn1 = fmaxf(m1, t1);
        float al0 = __expf(m0 - mn0), al1 = __expf(m1 - mn1);
        m0 = mn0; m1 = mn1;

        float sum0 = 0.0f, sum1 = 0.0f;
        uint32_t pah[4][4], pal[4][4];
        #pragma unroll
        for (int kp = 0; kp < 4; ++kp) {
            float p00 = __expf(sc[2 * kp][0] - mn0);
            float p01 = __expf(sc[2 * kp][1] - mn0);
            float p02 = __expf(sc[2 * kp][2] - mn1);
            float p03 = __expf(sc[2 * kp][3] - mn1);
            float p10 = __expf(sc[2 * kp + 1][0] - mn0);
            float p11 = __expf(sc[2 * kp + 1][1] - mn0);
            float p12 = __expf(sc[2 * kp + 1][2] - mn1);
            float p13 = __expf(sc[2 * kp + 1][3] - mn1);
            sum0 += p00 + p01 + p10 + p11;
            sum1 += p02 + p03 + p12 + p13;
            split2h(p00, p01, pah[kp][0], pal[kp][0]);
            split2h(p02, p03, pah[kp][1], pal[kp][1]);
            split2h(p10, p11, pah[kp][2], pal[kp][2]);
            split2h(p12, p13, pah[kp][3], pal[kp][3]);
        }
        sum0 += __shfl_xor_sync(0xffffffffu, sum0, 1);
        sum0 += __shfl_xor_sync(0xffffffffu, sum0, 2);
        sum1 += __shfl_xor_sync(0xffffffffu, sum1, 1);
        sum1 += __shfl_xor_sync(0xffffffffu, sum1, 2);
        l0 = l0 * al0 + sum0;
        l1 = l1 * al1 + sum1;
        #pragma unroll
        for (int ni = 0; ni < 8; ++ni) {
            oacc[ni][0] *= al0; oacc[ni][1] *= al0;
            oacc[ni][2] *= al1; oacc[ni][3] *= al1;
        }

        #pragma unroll
        for (int ks = 0; ks < 4; ++ks) {
            #pragma unroll
            for (int j2 = 0; j2 < 4; ++j2) {
                uint32_t vh0, vh1, vh2, vh3;
                uint32_t voff = st + AT_V + SWZ128B(
                    (uint32_t)((ks * 16 + v_rsel) * 128 + (v_csel + j2 * 16) * 2));
                LDM_X4T(vh0, vh1, vh2, vh3, voff);
                MMAH16(oacc[2 * j2],     pah[ks], vh0, vh1);
                MMAH16(oacc[2 * j2],     pal[ks], vh0, vh1);
                MMAH16(oacc[2 * j2 + 1], pah[ks], vh2, vh3);
                MMAH16(oacc[2 * j2 + 1], pal[ks], vh2, vh3);
            }
        }
        __syncthreads();
    }

    float inv0 = 1.0f / l0, inv1 = 1.0f / l1;
    int grow = qt * 64 + wid * 16 + gid;
    #pragma unroll
    for (int ni = 0; ni < 8; ++ni) {
        size_t i0 = (rowbase + grow) * (size_t)DMODEL + h * HDIM + ni * 8 + tig * 2;
        size_t i1 = i0 + 8 * (size_t)DMODEL;
        uint32_t hh, ll;
        split2h(oacc[ni][0] * inv0, oacc[ni][1] * inv0, hh, ll);
        *(uint32_t*)&Oh[i0] = hh;
        *(uint32_t*)&Ol[i0] = ll;
        split2h(oacc[ni][2] * inv1, oacc[ni][3] * inv1, hh, ll);
        *(uint32_t*)&Oh[i1] = hh;
        *(uint32_t*)&Ol[i1] = ll;
    }
}

// ---------------- launch -------------------------------------------
static void* sym_addr(const void* sym) {
    void* p = nullptr;
    cudaGetSymbolAddress(&p, sym);
    return p;
}

extern "C" void kernel_launch(void* const* d_in, const int* in_sizes, int n_in,
                              void* d_out, int out_size) {
    const float* x     = (const float*)d_in[0];
    const float* ln1_g = (const float*)d_in[1];
    const float* ln1_b = (const float*)d_in[2];
    const float* Wq    = (const float*)d_in[3];
    const float* Wk    = (const float*)d_in[4];
    const float* Wv    = (const float*)d_in[5];
    const float* Wo    = (const float*)d_in[6];
    const float* ln2_g = (const float*)d_in[7];
    const float* ln2_b = (const float*)d_in[8];
    const float* W1    = (const float*)d_in[9];
    const float* b1    = (const float*)d_in[10];
    const float* W2    = (const float*)d_in[11];
    const float* b2    = (const float*)d_in[12];
    float* out = (float*)d_out;

    float* x2 = (float*)sym_addr(g_x2);
    __half* lnh  = (__half*)sym_addr(g_lnh);
    __half* lnl  = (__half*)sym_addr(g_lnl);
    __half* qkvh = (__half*)sym_addr(g_qkvh);
    __half* qkvl = (__half*)sym_addr(g_qkvl);
    __half* ctxh = (__half*)sym_addr(g_ctxh);
    __half* ctxl = (__half*)sym_addr(g_ctxl);
    __half* ffh  = (__half*)sym_addr(g_ffh);
    __half* ffl  = (__half*)sym_addr(g_ffl);

    __half* Bqkv = (__half*)sym_addr(g_Bqkv);
    __half* Bo   = (__half*)sym_addr(g_Bo);
    __half* B1   = (__half*)sym_addr(g_B1);
    __half* B2   = (__half*)sym_addr(g_B2);

    cudaFuncSetAttribute(hgemm_kernel<0, 0, 0, 1>,
                         cudaFuncAttributeMaxDynamicSharedMemorySize, HG_SMEM_BYTES);
    cudaFuncSetAttribute(hgemm_kernel<0, 0, 1, 0>,
                         cudaFuncAttributeMaxDynamicSharedMemorySize, HG_SMEM_BYTES);
    cudaFuncSetAttribute(hgemm_kernel<1, 1, 0, 1>,
                         cudaFuncAttributeMaxDynamicSharedMemorySize, HG_SMEM_BYTES);
    cudaFuncSetAttribute(hgemm_kernel<0, 1, 1, 0>,
                         cudaFuncAttributeMaxDynamicSharedMemorySize, HG_SMEM_BYTES);
    cudaFuncSetAttribute(attn_kernel,
                         cudaFuncAttributeMaxDynamicSharedMemorySize, AT_SMEM);

    dim3 blk128(128), blk256(256);
    dim3 gqkv(DM3 / 128, MROWS / 128);         // (24, 32)
    dim3 g1k(DMODEL / 128, MROWS / 128);       // (8, 32)
    dim3 g2k(2 * DMODEL / 128, MROWS / 128);   // (16, 32)

    // 0: weight prep (fp16 hi-only transposed weights)
    wsplit_all_kernel<<<8192, blk256>>>(Wq, Wk, Wv, Bqkv, Wo, Bo,
                                        W1, B1, W2, B2);
    // 1: LN1 -> fp16 hi/lo
    ln_kernel<<<MROWS, blk256>>>(x, ln1_g, ln1_b, lnh, lnl);
    // 2: merged QKV projection -> fp16 hi/lo
    hgemm_kernel<0, 0, 0, 1><<<gqkv, blk256, HG_SMEM_BYTES>>>(
        lnh, lnl, Bqkv, nullptr, nullptr, nullptr, qkvh, qkvl,
        MROWS, DM3, DMODEL);
    // 3: attention (fp16 2-product) -> ctx fp16 hi/lo
    attn_kernel<<<dim3(32, 32), blk128, AT_SMEM>>>(qkvh, qkvl, ctxh, ctxl);
    // 4: output projection + residual(x) -> x2 fp32
    hgemm_kernel<0, 0, 1, 0><<<g1k, blk256, HG_SMEM_BYTES>>>(
        ctxh, ctxl, Bo, nullptr, x, x2, nullptr, nullptr,
        MROWS, DMODEL, DMODEL);
    // 5: LN2 -> fp16 hi/lo
    ln_kernel<<<MROWS, blk256>>>(x2, ln2_g, ln2_b, lnh, lnl);
    // 6: FFN up + bias + GELU -> ff fp16 hi/lo
    hgemm_kernel<1, 1, 0, 1><<<g2k, blk256, HG_SMEM_BYTES>>>(
        lnh, lnl, B1, b1, nullptr, nullptr, ffh, ffl,
        MROWS, 2 * DMODEL, DMODEL);
    // 7: FFN down + bias + residual(x2) -> out fp32
    hgemm_kernel<0, 1, 1, 0><<<g1k, blk256, HG_SMEM_BYTES>>>(
        ffh, ffl, B2, b2, x2, out, nullptr, nullptr,
        MROWS, DMODEL, 2 * DMODEL);
}

// round 16
// speedup vs baseline: 1.6702x; 1.1429x over previous
#include <cuda_runtime.h>
#include <cuda_bf16.h>
#include <cuda_fp16.h>
#include <math.h>
#include <stdint.h>

#define DMODEL 1024
#define SEQT   2048
#define BATCH  2
#define MROWS  4096   // BATCH * SEQT
#define NHEAD  16
#define HDIM   64
#define DM3    (3 * DMODEL)

// ---------------- scratch (static device allocations) ----------------
__device__ float g_x2 [MROWS * DMODEL];
__device__ __half g_lnh [MROWS * DMODEL], g_lnl [MROWS * DMODEL];
__device__ __half g_qkvh[MROWS * DM3],    g_qkvl[MROWS * DM3];
__device__ __half g_ctxh[MROWS * DMODEL];
__device__ __half g_ffh [MROWS * 2 * DMODEL];

// transposed weights: [N][K] fp16 hi-only
__device__ __half g_Bqkv[DM3 * DMODEL];
__device__ __half g_Bo[DMODEL * DMODEL];
__device__ __half g_B1[2 * DMODEL * DMODEL];
__device__ __half g_B2[2 * DMODEL * DMODEL];

// ---------------- helpers --------------------------------------------
__device__ __forceinline__ uint32_t smem_u32(const void* p) {
    uint32_t a;
    asm("{ .reg .u64 t; cvta.to.shared.u64 t, %1; cvt.u32.u64 %0, t; }"
        : "=r"(a) : "l"(p));
    return a;
}
__device__ __forceinline__ float gelu_exact(float x) {
    return 0.5f * x * (1.0f + erff(x * 0.70710678118654752f));
}
// fp16 hi/lo split
__device__ __forceinline__ void split2h(float x, float y, uint32_t& h, uint32_t& l) {
    __half2 hh = __float22half2_rn(make_float2(x, y));
    float2 f = __half22float2(hh);
    __half2 ll = __float22half2_rn(make_float2(x - f.x, y - f.y));
    h = *(uint32_t*)&hh;
    l = *(uint32_t*)&ll;
}
__device__ __forceinline__ uint32_t pack_h2(float x, float y) {
    __half2 hh = __float22half2_rn(make_float2(x, y));
    return *(uint32_t*)&hh;
}

#define LDM_X4(r0, r1, r2, r3, addr) \
    asm volatile("ldmatrix.sync.aligned.m8n8.x4.shared.b16 {%0,%1,%2,%3}, [%4];" \
        : "=r"(r0), "=r"(r1), "=r"(r2), "=r"(r3) : "r"(addr))
#define LDM_X4T(r0, r1, r2, r3, addr) \
    asm volatile("ldmatrix.sync.aligned.m8n8.x4.trans.shared.b16 {%0,%1,%2,%3}, [%4];" \
        : "=r"(r0), "=r"(r1), "=r"(r2), "=r"(r3) : "r"(addr))

// fp16 MMA
#define MMAH16(d, a, b0, b1) \
    asm volatile("mma.sync.aligned.m16n8k16.row.col.f32.f16.f16.f32 " \
        "{%0,%1,%2,%3}, {%4,%5,%6,%7}, {%8,%9}, {%0,%1,%2,%3};" \
        : "+f"((d)[0]), "+f"((d)[1]), "+f"((d)[2]), "+f"((d)[3]) \
        : "r"((a)[0]), "r"((a)[1]), "r"((a)[2]), "r"((a)[3]), \
          "r"(b0), "r"(b1))

#define CP16(dst, src) \
    asm volatile("cp.async.cg.shared.global [%0], [%1], 16;" \
        :: "r"(dst), "l"(src))
#define CP_COMMIT() asm volatile("cp.async.commit_group;")
#define CP_WAIT2()  asm volatile("cp.async.wait_group 2;")
#define CP_WAIT1()  asm volatile("cp.async.wait_group 1;")
#define CP_WAIT0()  asm volatile("cp.async.wait_group 0;")

// 64B-row tile swizzle for GEMM smem.
#define SWZ64(off) ((off) ^ ((((off) >> 7) & 3u) << 4))
// 128B-row tile swizzle (standard SW128) for attention K/V smem.
#define SWZ128B(off) ((off) ^ (((off) >> 3) & 0x70u))

// ---------------- weight prep: transpose -> fp16 hi-only -------------
__global__ void __launch_bounds__(256) wsplit_all_kernel(
    const float* __restrict__ Wq, const float* __restrict__ Wk,
    const float* __restrict__ Wv, __half* __restrict__ Bqkv,
    const float* __restrict__ Wo, __half* __restrict__ Bo,
    const float* __restrict__ W1, __half* __restrict__ B1,
    const float* __restrict__ W2, __half* __restrict__ B2) {
    __shared__ float t[32][33];
    int bid = blockIdx.x;
    const float* W;
    __half* Th;
    int K, N, k0, n0, nout;
    if (bid < 4096) {
        int w = bid >> 10, lb = bid & 1023;
        K = DMODEL; N = DMODEL;
        k0 = (lb & 31) * 32; n0 = (lb >> 5) * 32;
        if (w < 3) {
            W = (w == 0) ? Wq : (w == 1) ? Wk : Wv;
            Th = Bqkv;
            nout = n0 + w * DMODEL;
        } else {
            W = Wo; Th = Bo; nout = n0;
        }
    } else if (bid < 6144) {
        int lb = bid - 4096;
        K = DMODEL; N = 2 * DMODEL;
        k0 = (lb & 31) * 32; n0 = (lb >> 5) * 32;
        W = W1; Th = B1; nout = n0;
    } else {
        int lb = bid - 6144;
        K = 2 * DMODEL; N = DMODEL;
        k0 = (lb & 63) * 32; n0 = (lb >> 6) * 32;
        W = W2; Th = B2; nout = n0;
    }
    int tx = threadIdx.x & 31, ty = threadIdx.x >> 5;
    #pragma unroll
    for (int i = 0; i < 4; ++i)
        t[ty + i * 8][tx] = W[(size_t)(k0 + ty + i * 8) * N + n0 + tx];
    __syncthreads();
    #pragma unroll
    for (int i = 0; i < 4; ++i) {
        int n = nout + ty + i * 8, k = k0 + tx;
        Th[(size_t)n * K + k] = __float2half_rn(t[tx][ty + i * 8]);
    }
}

// ---------------- LayerNorm -> fp16 hi/lo ----------------------------
__global__ void __launch_bounds__(256) ln_kernel(const float* __restrict__ x,
                                                 const float* __restrict__ g,
                                                 const float* __restrict__ b,
                                                 __half* __restrict__ outh,
                                                 __half* __restrict__ outl) {
    int row = blockIdx.x;
    int tid = threadIdx.x;
    const float4* xr = (const float4*)(x + (size_t)row * DMODEL);
    float4 v = xr[tid];
    float s  = v.x + v.y + v.z + v.w;
    float ss = v.x * v.x + v.y * v.y + v.z * v.z + v.w * v.w;
    #pragma unroll
    for (int o = 16; o > 0; o >>= 1) {
        s  += __shfl_xor_sync(0xffffffffu, s,  o);
        ss += __shfl_xor_sync(0xffffffffu, ss, o);
    }
    __shared__ float sh[16];
    int w = tid >> 5;
    if ((tid & 31) == 0) { sh[w] = s; sh[8 + w] = ss; }
    __syncthreads();
    if (tid < 32) {
        float a  = (tid < 8) ? sh[tid]     : 0.0f;
        float a2 = (tid < 8) ? sh[8 + tid] : 0.0f;
        #pragma unroll
        for (int o = 4; o > 0; o >>= 1) {
            a  += __shfl_xor_sync(0xffffffffu, a,  o);
            a2 += __shfl_xor_sync(0xffffffffu, a2, o);
        }
        if (tid == 0) { sh[0] = a; sh[1] = a2; }
    }
    __syncthreads();
    float mean = sh[0] * (1.0f / DMODEL);
    float var  = sh[1] * (1.0f / DMODEL) - mean * mean;
    float rstd = rsqrtf(var + 1e-5f);
    float4 gg = ((const float4*)g)[tid];
    float4 bb = ((const float4*)b)[tid];
    float o0 = (v.x - mean) * rstd * gg.x + bb.x;
    float o1 = (v.y - mean) * rstd * gg.y + bb.y;
    float o2 = (v.z - mean) * rstd * gg.z + bb.z;
    float o3 = (v.w - mean) * rstd * gg.w + bb.w;
    uint2 h, l;
    split2h(o0, o1, h.x, l.x);
    split2h(o2, o3, h.y, l.y);
    ((uint2*)(outh + (size_t)row * DMODEL))[tid] = h;
    ((uint2*)(outl + (size_t)row * DMODEL))[tid] = l;
}

// ---------------- fp16 GEMM: 256 thr, 3-stage swizzled ---------------
// HASLO=1: 2-product (AhBh + AlBh), stage = Ah+Al+Bh = 24KB.
// HASLO=0: 1-product (AhBh only),   stage = Ah+Bh    = 16KB.
// OSPLIT: 0 = fp32 C, 1 = fp16 hi+lo, 2 = fp16 hi-only.
template <int GELU, int HAS_BIAS, int HAS_RES, int OSPLIT, int HASLO>
__global__ void __launch_bounds__(256, 2) hgemm_kernel(
    const __half* __restrict__ Ah, const __half* __restrict__ Al,
    const __half* __restrict__ Bh,
    const float* __restrict__ bias, const float* __restrict__ res,
    float* __restrict__ C, __half* __restrict__ Ch,
    __half* __restrict__ Cl, int M, int N, int K) {
    constexpr uint32_t AL_OFF = 8192;
    constexpr uint32_t B_OFF  = HASLO ? 16384 : 8192;
    constexpr uint32_t STG    = HASLO ? 24576 : 16384;
    extern __shared__ __align__(16) char smem[];
    uint32_t uS = smem_u32(smem);

    int tid = threadIdx.x;
    int lane = tid & 31, wid = tid >> 5;
    int wm = wid >> 2, wn = wid & 3;
    int bm = blockIdx.y * 128, bn = blockIdx.x * 128;

    float acc[4][4][4];
    #pragma unroll
    for (int i = 0; i < 4; ++i)
        #pragma unroll
        for (int j = 0; j < 4; ++j)
            #pragma unroll
            for (int k = 0; k < 4; ++k) acc[i][j][k] = 0.0f;

    int q = lane >> 3, rr = lane & 7;
    int a_row = wm * 64 + (q & 1) * 8 + rr;
    int a_cb  = 16 * (q >> 1);
    int b_row = wn * 32 + (q >> 1) * 8 + rr;
    int b_cb  = 16 * (q & 1);

    int lr = tid >> 2, lck = (tid & 3) << 4;
    const int NC = K >> 5;

    auto load_chunk = [&](int c, int s) {
        uint32_t sb = uS + (uint32_t)s * STG;
        int kc = c << 5;
        #pragma unroll
        for (int i = 0; i < 2; ++i) {
            int r = lr + i * 64;
            uint32_t d = sb + SWZ64((uint32_t)(r * 64 + lck));
            CP16(d, Ah + (size_t)(bm + r) * K + kc + (lck >> 1));
            if (HASLO)
                CP16(d + AL_OFF, Al + (size_t)(bm + r) * K + kc + (lck >> 1));
        }
        #pragma unroll
        for (int i = 0; i < 2; ++i) {
            int r = lr + i * 64;
            uint32_t d = sb + B_OFF + SWZ64((uint32_t)(r * 64 + lck));
            CP16(d, Bh + (size_t)(bn + r) * K + kc + (lck >> 1));
        }
        CP_COMMIT();
    };

    load_chunk(0, 0);
    if (NC > 1) load_chunk(1, 1);

    for (int c = 0; c < NC; ++c) {
        if (c + 2 < NC) { load_chunk(c + 2, (c + 2) % 3); CP_WAIT2(); }
        else if (c + 1 < NC) { CP_WAIT1(); }
        else { CP_WAIT0(); }
        __syncthreads();

        uint32_t sb = uS + (uint32_t)(c % 3) * STG;
        #pragma unroll
        for (int ks = 0; ks < 2; ++ks) {
            uint32_t ahf[4][4], alf[4][4];
            #pragma unroll
            for (int mi = 0; mi < 4; ++mi) {
                uint32_t off = sb + SWZ64(
                    (uint32_t)((a_row + mi * 16) * 64 + a_cb + ks * 32));
                LDM_X4(ahf[mi][0], ahf[mi][1], ahf[mi][2], ahf[mi][3], off);
                if (HASLO)
                    LDM_X4(alf[mi][0], alf[mi][1], alf[mi][2], alf[mi][3],
                           off + AL_OFF);
            }
            #pragma unroll
            for (int j2 = 0; j2 < 2; ++j2) {
                uint32_t bhf[2][2];
                uint32_t off = sb + B_OFF + SWZ64(
                    (uint32_t)((b_row + j2 * 16) * 64 + b_cb + ks * 32));
                LDM_X4(bhf[0][0], bhf[0][1], bhf[1][0], bhf[1][1], off);
                #pragma unroll
                for (int mi = 0; mi < 4; ++mi)
                    #pragma unroll
                    for (int nj = 0; nj < 2; ++nj) {
                        int ni = j2 * 2 + nj;
                        MMAH16(acc[mi][ni], ahf[mi], bhf[nj][0], bhf[nj][1]);
                        if (HASLO)
                            MMAH16(acc[mi][ni], alf[mi], bhf[nj][0], bhf[nj][1]);
                    }
            }
        }
        __syncthreads();
    }

    int gid = lane >> 2, tig = lane & 3;
    #pragma unroll
    for (int mi = 0; mi < 4; ++mi) {
        #pragma unroll
        for (int ni = 0; ni < 4; ++ni) {
            int row0 = bm + wm * 64 + mi * 16 + gid;
            int col  = bn + wn * 32 + ni * 8 + tig * 2;
            float c0 = acc[mi][ni][0], c1 = acc[mi][ni][1];
            float c2 = acc[mi][ni][2], c3 = acc[mi][ni][3];
            if (HAS_BIAS) {
                float b0 = bias[col], b1v = bias[col + 1];
                c0 += b0; c1 += b1v; c2 += b0; c3 += b1v;
            }
            if (GELU) {
                c0 = gelu_exact(c0); c1 = gelu_exact(c1);
                c2 = gelu_exact(c2); c3 = gelu_exact(c3);
            }
            if (HAS_RES) {
                float2 r0 = *(const float2*)&res[(size_t)row0 * N + col];
                float2 r1 = *(const float2*)&res[(size_t)(row0 + 8) * N + col];
                c0 += r0.x; c1 += r0.y; c2 += r1.x; c3 += r1.y;
            }
            if (OSPLIT == 1) {
                uint32_t h0, l0, h1, l1;
                split2h(c0, c1, h0, l0);
                split2h(c2, c3, h1, l1);
                *(uint32_t*)&Ch[(size_t)row0 * N + col] = h0;
                *(uint32_t*)&Cl[(size_t)row0 * N + col] = l0;
                *(uint32_t*)&Ch[(size_t)(row0 + 8) * N + col] = h1;
                *(uint32_t*)&Cl[(size_t)(row0 + 8) * N + col] = l1;
            } else if (OSPLIT == 2) {
                *(uint32_t*)&Ch[(size_t)row0 * N + col] = pack_h2(c0, c1);
                *(uint32_t*)&Ch[(size_t)(row0 + 8) * N + col] = pack_h2(c2, c3);
            } else {
                float2 o0; o0.x = c0; o0.y = c1;
                float2 o1; o1.x = c2; o1.y = c3;
                *(float2*)&C[(size_t)row0 * N + col] = o0;
                *(float2*)&C[(size_t)(row0 + 8) * N + col] = o1;
            }
        }
    }
}

// ---------------- Tensor-core flash attention (fp16, 2-product) ------
// Q hi/lo in regs; K/V hi-only in smem. Output ctx hi-only.
#define AT_V     8192
#define AT_STAGE 16384
#define AT_SMEM  (2 * AT_STAGE)  // 32768

__global__ void __launch_bounds__(128, 3) attn_kernel(
    const __half* __restrict__ QKVh, const __half* __restrict__ QKVl,
    __half* __restrict__ Oh) {
    extern __shared__ __align__(16) char smem[];
    uint32_t uS = smem_u32(smem);

    int qt = 31 - (int)blockIdx.x;   // heavy-first
    int bh = blockIdx.y;
    int b = bh >> 4, h = bh & 15;
    int tid = threadIdx.x, lane = tid & 31, wid = tid >> 5;
    int gid = lane >> 2, tig = lane & 3;
    int q = lane >> 3, rr = lane & 7;

    size_t rowbase = (size_t)b * SEQT;

    auto ld_kv = [&](uint32_t dst, int trow, int cbase) {
        #pragma unroll
        for (int i = 0; i < 4; ++i) {
            int idx = tid + i * 128;
            int r = idx >> 3, c8 = (idx & 7) << 3;
            CP16(dst + SWZ128B((uint32_t)(r * 128 + c8 * 2)),
                 QKVh + (rowbase + trow + r) * (size_t)DM3 + cbase + h * HDIM + c8);
        }
    };

    ld_kv(uS, 0, DMODEL);
    ld_kv(uS + AT_V, 0, 2 * DMODEL);
    CP_COMMIT();

    uint32_t qh[4][4], ql[4][4];
    {
        int row0 = qt * 64 + wid * 16 + gid;
        size_t base0 = (rowbase + row0) * (size_t)DM3 + h * HDIM;
        size_t base8 = base0 + 8 * (size_t)DM3;
        #pragma unroll
        for (int ks = 0; ks < 4; ++ks) {
            int c0 = ks * 16 + 2 * tig;
            qh[ks][0] = *(const uint32_t*)&QKVh[base0 + c0];
            qh[ks][1] = *(const uint32_t*)&QKVh[base8 + c0];
            qh[ks][2] = *(const uint32_t*)&QKVh[base0 + c0 + 8];
            qh[ks][3] = *(const uint32_t*)&QKVh[base8 + c0 + 8];
            ql[ks][0] = *(const uint32_t*)&QKVl[base0 + c0];
            ql[ks][1] = *(const uint32_t*)&QKVl[base8 + c0];
            ql[ks][2] = *(const uint32_t*)&QKVl[base0 + c0 + 8];
            ql[ks][3] = *(const uint32_t*)&QKVl[base8 + c0 + 8];
        }
    }

    float oacc[8][4];
    #pragma unroll
    for (int i = 0; i < 8; ++i)
        #pragma unroll
        for (int j = 0; j < 4; ++j) oacc[i][j] = 0.0f;
    float m0 = -1e30f, m1 = -1e30f, l0 = 0.0f, l1 = 0.0f;

    int b_rsel = (q >> 1) * 8 + rr;
    int b_csel = (q & 1) * 8;
    int v_rsel = (q & 1) * 8 + rr;
    int v_csel = (q >> 1) * 8;

    for (int kt = 0; kt <= qt; ++kt) {
        uint32_t st = uS + (uint32_t)(kt & 1) * AT_STAGE;
        if (kt < qt) {
            uint32_t s2 = uS + (uint32_t)((kt + 1) & 1) * AT_STAGE;
            ld_kv(s2, (kt + 1) * 64, DMODEL);
            ld_kv(s2 + AT_V, (kt + 1) * 64, 2 * DMODEL);
            CP_COMMIT();
            CP_WAIT1();
        } else {
            CP_WAIT0();
        }
        __syncthreads();

        float sc[8][4];
        #pragma unroll
        for (int i = 0; i < 8; ++i)
            #pragma unroll
            for (int j = 0; j < 4; ++j) sc[i][j] = 0.0f;

        #pragma unroll
        for (int ks = 0; ks < 4; ++ks) {
            #pragma unroll
            for (int j2 = 0; j2 < 4; ++j2) {
                uint32_t kh0, kh1, kh2, kh3;
                uint32_t boff = st + SWZ128B(
                    (uint32_t)((j2 * 16 + b_rsel) * 128 + (b_csel + ks * 16) * 2));
                LDM_X4(kh0, kh1, kh2, kh3, boff);
                MMAH16(sc[2 * j2],     qh[ks], kh0, kh1);
                MMAH16(sc[2 * j2],     ql[ks], kh0, kh1);
                MMAH16(sc[2 * j2 + 1], qh[ks], kh2, kh3);
                MMAH16(sc[2 * j2 + 1], ql[ks], kh2, kh3);
            }
        }

        #pragma unroll
        for (int ni = 0; ni < 8; ++ni) {
            sc[ni][0] *= 0.125f; sc[ni][1] *= 0.125f;
            sc[ni][2] *= 0.125f; sc[ni][3] *= 0.125f;
        }
        if (kt == qt) {
            int r0 = wid * 16 + gid, r1 = r0 + 8;
            #pragma unroll
            for (int ni = 0; ni < 8; ++ni) {
                int c0 = ni * 8 + tig * 2, c1 = c0 + 1;
                if (c0 > r0) sc[ni][0] = -1e30f;
                if (c1 > r0) sc[ni][1] = -1e30f;
                if (c0 > r1) sc[ni][2] = -1e30f;
                if (c1 > r1) sc[ni][3] = -1e30f;
            }
        }

        float t0 = -1e30f, t1 = -1e30f;
        #pragma unroll
        for (int ni = 0; ni < 8; ++ni) {
            t0 = fmaxf(t0, fmaxf(sc[ni][0], sc[ni][1]));
            t1 = fmaxf(t1, fmaxf(sc[ni][2], sc[ni][3]));
        }
        t0 = fmaxf(t0, __shfl_xor_sync(0xffffffffu, t0, 1));
        t0 = fmaxf(t0, __shfl_xor_sync(0xffffffffu, t0, 2));
        t1 = fmaxf(t1, __shfl_xor_sync(0xffffffffu, t1, 1));
        t1 = fmaxf(t1, __shfl_xor_sync(0xffffffffu, t1, 2));
        float mn0 = fmaxf(m0, t0), mn1 = fmaxf(m1, t1);
        float al0 = __expf(m0 - mn0), al1 = __expf(m1 - mn1);
        m0 = mn0; m1 = mn1;

        float sum0 = 0.0f, sum1 = 0.0f;
        uint32_t pah[4][4], pal[4][4];
        #pragma unroll
        for (int kp = 0; kp < 4; ++kp) {
            float p00 = __expf(sc[2 * kp][0] - mn0);
            float p01 = __expf(sc[2 * kp][1] - mn0);
            float p02 = __expf(sc[2 * kp][2] - mn1);
            float p03 = __expf(sc[2 * kp][3] - mn1);
            float p10 = __expf(sc[2 * kp + 1][0] - mn0);
            float p11 = __expf(sc[2 * kp + 1][1] - mn0);
            float p12 = __expf(sc[2 * kp + 1][2] - mn1);
            float p13 = __expf(sc[2 * kp + 1][3] - mn1);
            sum0 += p00 + p01 + p10 + p11;
            sum1 += p02 + p03 + p12 + p13;
            split2h(p00, p01, pah[kp][0], pal[kp][0]);
            split2h(p02, p03, pah[kp][1], pal[kp][1]);
            split2h(p10, p11, pah[kp][2], pal[kp][2]);
            split2h(p12, p13, pah[kp][3], pal[kp][3]);
        }
        sum0 += __shfl_xor_sync(0xffffffffu, sum0, 1);
        sum0 += __shfl_xor_sync(0xffffffffu, sum0, 2);
        sum1 += __shfl_xor_sync(0xffffffffu, sum1, 1);
        sum1 += __shfl_xor_sync(0xffffffffu, sum1, 2);
        l0 = l0 * al0 + sum0;
        l1 = l1 * al1 + sum1;
        #pragma unroll
        for (int ni = 0; ni < 8; ++ni) {
            oacc[ni][0] *= al0; oacc[ni][1] *= al0;
            oacc[ni][2] *= al1; oacc[ni][3] *= al1;
        }

        #pragma unroll
        for (int ks = 0; ks < 4; ++ks) {
            #pragma unroll
            for (int j2 = 0; j2 < 4; ++j2) {
                uint32_t vh0, vh1, vh2, vh3;
                uint32_t voff = st + AT_V + SWZ128B(
                    (uint32_t)((ks * 16 + v_rsel) * 128 + (v_csel + j2 * 16) * 2));
                LDM_X4T(vh0, vh1, vh2, vh3, voff);
                MMAH16(oacc[2 * j2],     pah[ks], vh0, vh1);
                MMAH16(oacc[2 * j2],     pal[ks], vh0, vh1);
                MMAH16(oacc[2 * j2 + 1], pah[ks], vh2, vh3);
                MMAH16(oacc[2 * j2 + 1], pal[ks], vh2, vh3);
            }
        }
        __syncthreads();
    }

    float inv0 = 1.0f / l0, inv1 = 1.0f / l1;
    int grow = qt * 64 + wid * 16 + gid;
    #pragma unroll
    for (int ni = 0; ni < 8; ++ni) {
        size_t i0 = (rowbase + grow) * (size_t)DMODEL + h * HDIM + ni * 8 + tig * 2;
        size_t i1 = i0 + 8 * (size_t)DMODEL;
        *(uint32_t*)&Oh[i0] = pack_h2(oacc[ni][0] * inv0, oacc[ni][1] * inv0);
        *(uint32_t*)&Oh[i1] = pack_h2(oacc[ni][2] * inv1, oacc[ni][3] * inv1);
    }
}

// ---------------- launch -------------------------------------------
static void* sym_addr(const void* sym) {
    void* p = nullptr;
    cudaGetSymbolAddress(&p, sym);
    return p;
}

extern "C" void kernel_launch(void* const* d_in, const int* in_sizes, int n_in,
                              void* d_out, int out_size) {
    const float* x     = (const float*)d_in[0];
    const float* ln1_g = (const float*)d_in[1];
    const float* ln1_b = (const float*)d_in[2];
    const float* Wq    = (const float*)d_in[3];
    const float* Wk    = (const float*)d_in[4];
    const float* Wv    = (const float*)d_in[5];
    const float* Wo    = (const float*)d_in[6];
    const float* ln2_g = (const float*)d_in[7];
    const float* ln2_b = (const float*)d_in[8];
    const float* W1    = (const float*)d_in[9];
    const float* b1    = (const float*)d_in[10];
    const float* W2    = (const float*)d_in[11];
    const float* b2    = (const float*)d_in[12];
    float* out = (float*)d_out;

    float* x2 = (float*)sym_addr(g_x2);
    __half* lnh  = (__half*)sym_addr(g_lnh);
    __half* lnl  = (__half*)sym_addr(g_lnl);
    __half* qkvh = (__half*)sym_addr(g_qkvh);
    __half* qkvl = (__half*)sym_addr(g_qkvl);
    __half* ctxh = (__half*)sym_addr(g_ctxh);
    __half* ffh  = (__half*)sym_addr(g_ffh);

    __half* Bqkv = (__half*)sym_addr(g_Bqkv);
    __half* Bo   = (__half*)sym_addr(g_Bo);
    __half* B1   = (__half*)sym_addr(g_B1);
    __half* B2   = (__half*)sym_addr(g_B2);

    cudaFuncSetAttribute(hgemm_kernel<0, 0, 0, 1, 1>,
                         cudaFuncAttributeMaxDynamicSharedMemorySize, 3 * 24576);
    cudaFuncSetAttribute(hgemm_kernel<1, 1, 0, 2, 1>,
                         cudaFuncAttributeMaxDynamicSharedMemorySize, 3 * 24576);
    cudaFuncSetAttribute(hgemm_kernel<0, 0, 1, 0, 0>,
                         cudaFuncAttributeMaxDynamicSharedMemorySize, 3 * 16384);
    cudaFuncSetAttribute(hgemm_kernel<0, 1, 1, 0, 0>,
                         cudaFuncAttributeMaxDynamicSharedMemorySize, 3 * 16384);
    cudaFuncSetAttribute(attn_kernel,
                         cudaFuncAttributeMaxDynamicSharedMemorySize, AT_SMEM);

    dim3 blk128(128), blk256(256);
    dim3 gqkv(DM3 / 128, MROWS / 128);         // (24, 32)
    dim3 g1k(DMODEL / 128, MROWS / 128);       // (8, 32)
    dim3 g2k(2 * DMODEL / 128, MROWS / 128);   // (16, 32)

    // 0: weight prep (fp16 hi-only transposed weights)
    wsplit_all_kernel<<<8192, blk256>>>(Wq, Wk, Wv, Bqkv, Wo, Bo,
                                        W1, B1, W2, B2);
    // 1: LN1 -> fp16 hi/lo
    ln_kernel<<<MROWS, blk256>>>(x, ln1_g, ln1_b, lnh, lnl);
    // 2: merged QKV projection (2-product) -> fp16 hi/lo
    hgemm_kernel<0, 0, 0, 1, 1><<<gqkv, blk256, 3 * 24576>>>(
        lnh, lnl, Bqkv, nullptr, nullptr, nullptr, qkvh, qkvl,
        MROWS, DM3, DMODEL);
    // 3: attention (fp16 2-product) -> ctx fp16 hi-only
    attn_kernel<<<dim3(32, 32), blk128, AT_SMEM>>>(qkvh, qkvl, ctxh);
    // 4: output projection (1-product) + residual(x) -> x2 fp32
    hgemm_kernel<0, 0, 1, 0, 0><<<g1k, blk256, 3 * 16384>>>(
        ctxh, nullptr, Bo, nullptr, x, x2, nullptr, nullptr,
        MROWS, DMODEL, DMODEL);
    // 5: LN2 -> fp16 hi/lo
    ln_kernel<<<MROWS, blk256>>>(x2, ln2_g, ln2_b, lnh, lnl);
    // 6: FFN up (2-product) + bias + GELU -> ff fp16 hi-only
    hgemm_kernel<1, 1, 0, 2, 1><<<g2k, blk256, 3 * 24576>>>(
        lnh, lnl, B1, b1, nullptr, nullptr, ffh, nullptr,
        MROWS, 2 * DMODEL, DMODEL);
    // 7: FFN down (1-product) + bias + residual(x2) -> out fp32
    hgemm_kernel<0, 1, 1, 0, 0><<<g1k, blk256, 3 * 16384>>>(
        ffh, nullptr, B2, b2, x2, out, nullptr, nullptr,
        MROWS, DMODEL, 2 * DMODEL);
}

// round 17
// speedup vs baseline: 1.7489x; 1.0471x over previous
#include <cuda_runtime.h>
#include <cuda_bf16.h>
#include <cuda_fp16.h>
#include <math.h>
#include <stdint.h>

#define DMODEL 1024
#define SEQT   2048
#define BATCH  2
#define MROWS  4096   // BATCH * SEQT
#define NHEAD  16
#define HDIM   64
#define DM3    (3 * DMODEL)

// ---------------- scratch (static device allocations) ----------------
__device__ float g_x2 [MROWS * DMODEL];
__device__ __half g_lnh [MROWS * DMODEL], g_lnl [MROWS * DMODEL];
__device__ __half g_qkvh[MROWS * DM3],    g_qkvl[MROWS * DM3];
__device__ __half g_ctxh[MROWS * DMODEL];
__device__ __half g_ffh [MROWS * 2 * DMODEL];

// transposed weights: [N][K] fp16 hi-only
__device__ __half g_Bqkv[DM3 * DMODEL];
__device__ __half g_Bo[DMODEL * DMODEL];
__device__ __half g_B1[2 * DMODEL * DMODEL];
__device__ __half g_B2[2 * DMODEL * DMODEL];

// ---------------- helpers --------------------------------------------
__device__ __forceinline__ uint32_t smem_u32(const void* p) {
    uint32_t a;
    asm("{ .reg .u64 t; cvta.to.shared.u64 t, %1; cvt.u32.u64 %0, t; }"
        : "=r"(a) : "l"(p));
    return a;
}
__device__ __forceinline__ float gelu_exact(float x) {
    return 0.5f * x * (1.0f + erff(x * 0.70710678118654752f));
}
// fp16 hi/lo split
__device__ __forceinline__ void split2h(float x, float y, uint32_t& h, uint32_t& l) {
    __half2 hh = __float22half2_rn(make_float2(x, y));
    float2 f = __half22float2(hh);
    __half2 ll = __float22half2_rn(make_float2(x - f.x, y - f.y));
    h = *(uint32_t*)&hh;
    l = *(uint32_t*)&ll;
}
__device__ __forceinline__ uint32_t pack_h2(float x, float y) {
    __half2 hh = __float22half2_rn(make_float2(x, y));
    return *(uint32_t*)&hh;
}

#define LDM_X4(r0, r1, r2, r3, addr) \
    asm volatile("ldmatrix.sync.aligned.m8n8.x4.shared.b16 {%0,%1,%2,%3}, [%4];" \
        : "=r"(r0), "=r"(r1), "=r"(r2), "=r"(r3) : "r"(addr))
#define LDM_X4T(r0, r1, r2, r3, addr) \
    asm volatile("ldmatrix.sync.aligned.m8n8.x4.trans.shared.b16 {%0,%1,%2,%3}, [%4];" \
        : "=r"(r0), "=r"(r1), "=r"(r2), "=r"(r3) : "r"(addr))

// fp16 MMA
#define MMAH16(d, a, b0, b1) \
    asm volatile("mma.sync.aligned.m16n8k16.row.col.f32.f16.f16.f32 " \
        "{%0,%1,%2,%3}, {%4,%5,%6,%7}, {%8,%9}, {%0,%1,%2,%3};" \
        : "+f"((d)[0]), "+f"((d)[1]), "+f"((d)[2]), "+f"((d)[3]) \
        : "r"((a)[0]), "r"((a)[1]), "r"((a)[2]), "r"((a)[3]), \
          "r"(b0), "r"(b1))

#define CP16(dst, src) \
    asm volatile("cp.async.cg.shared.global [%0], [%1], 16;" \
        :: "r"(dst), "l"(src))
#define CP_COMMIT() asm volatile("cp.async.commit_group;")
#define CP_WAIT2()  asm volatile("cp.async.wait_group 2;")
#define CP_WAIT1()  asm volatile("cp.async.wait_group 1;")
#define CP_WAIT0()  asm volatile("cp.async.wait_group 0;")

// 64B-row tile swizzle for GEMM smem.
#define SWZ64(off) ((off) ^ ((((off) >> 7) & 3u) << 4))
// 128B-row tile swizzle (standard SW128) for attention K/V smem.
#define SWZ128B(off) ((off) ^ (((off) >> 3) & 0x70u))

// ---------------- weight prep: transpose -> fp16 hi-only -------------
__global__ void __launch_bounds__(256) wsplit_all_kernel(
    const float* __restrict__ Wq, const float* __restrict__ Wk,
    const float* __restrict__ Wv, __half* __restrict__ Bqkv,
    const float* __restrict__ Wo, __half* __restrict__ Bo,
    const float* __restrict__ W1, __half* __restrict__ B1,
    const float* __restrict__ W2, __half* __restrict__ B2) {
    __shared__ float t[32][33];
    int bid = blockIdx.x;
    const float* W;
    __half* Th;
    int K, N, k0, n0, nout;
    if (bid < 4096) {
        int w = bid >> 10, lb = bid & 1023;
        K = DMODEL; N = DMODEL;
        k0 = (lb & 31) * 32; n0 = (lb >> 5) * 32;
        if (w < 3) {
            W = (w == 0) ? Wq : (w == 1) ? Wk : Wv;
            Th = Bqkv;
            nout = n0 + w * DMODEL;
        } else {
            W = Wo; Th = Bo; nout = n0;
        }
    } else if (bid < 6144) {
        int lb = bid - 4096;
        K = DMODEL; N = 2 * DMODEL;
        k0 = (lb & 31) * 32; n0 = (lb >> 5) * 32;
        W = W1; Th = B1; nout = n0;
    } else {
        int lb = bid - 6144;
        K = 2 * DMODEL; N = DMODEL;
        k0 = (lb & 63) * 32; n0 = (lb >> 6) * 32;
        W = W2; Th = B2; nout = n0;
    }
    int tx = threadIdx.x & 31, ty = threadIdx.x >> 5;
    #pragma unroll
    for (int i = 0; i < 4; ++i)
        t[ty + i * 8][tx] = W[(size_t)(k0 + ty + i * 8) * N + n0 + tx];
    __syncthreads();
    #pragma unroll
    for (int i = 0; i < 4; ++i) {
        int n = nout + ty + i * 8, k = k0 + tx;
        Th[(size_t)n * K + k] = __float2half_rn(t[tx][ty + i * 8]);
    }
}

// ---------------- LayerNorm -> fp16 hi/lo ----------------------------
__global__ void __launch_bounds__(256) ln_kernel(const float* __restrict__ x,
                                                 const float* __restrict__ g,
                                                 const float* __restrict__ b,
                                                 __half* __restrict__ outh,
                                                 __half* __restrict__ outl) {
    int row = blockIdx.x;
    int tid = threadIdx.x;
    const float4* xr = (const float4*)(x + (size_t)row * DMODEL);
    float4 v = xr[tid];
    float s  = v.x + v.y + v.z + v.w;
    float ss = v.x * v.x + v.y * v.y + v.z * v.z + v.w * v.w;
    #pragma unroll
    for (int o = 16; o > 0; o >>= 1) {
        s  += __shfl_xor_sync(0xffffffffu, s,  o);
        ss += __shfl_xor_sync(0xffffffffu, ss, o);
    }
    __shared__ float sh[16];
    int w = tid >> 5;
    if ((tid & 31) == 0) { sh[w] = s; sh[8 + w] = ss; }
    __syncthreads();
    if (tid < 32) {
        float a  = (tid < 8) ? sh[tid]     : 0.0f;
        float a2 = (tid < 8) ? sh[8 + tid] : 0.0f;
        #pragma unroll
        for (int o = 4; o > 0; o >>= 1) {
            a  += __shfl_xor_sync(0xffffffffu, a,  o);
            a2 += __shfl_xor_sync(0xffffffffu, a2, o);
        }
        if (tid == 0) { sh[0] = a; sh[1] = a2; }
    }
    __syncthreads();
    float mean = sh[0] * (1.0f / DMODEL);
    float var  = sh[1] * (1.0f / DMODEL) - mean * mean;
    float rstd = rsqrtf(var + 1e-5f);
    float4 gg = ((const float4*)g)[tid];
    float4 bb = ((const float4*)b)[tid];
    float o0 = (v.x - mean) * rstd * gg.x + bb.x;
    float o1 = (v.y - mean) * rstd * gg.y + bb.y;
    float o2 = (v.z - mean) * rstd * gg.z + bb.z;
    float o3 = (v.w - mean) * rstd * gg.w + bb.w;
    uint2 h, l;
    split2h(o0, o1, h.x, l.x);
    split2h(o2, o3, h.y, l.y);
    ((uint2*)(outh + (size_t)row * DMODEL))[tid] = h;
    ((uint2*)(outl + (size_t)row * DMODEL))[tid] = l;
}

// ---------------- fp16 GEMM: 256 thr, 3-stage swizzled ---------------
// HASLO=1: 2-product (AhBh + AlBh); HASLO=0: 1-product.
// OSPLIT: 0 = fp32 C, 1 = fp16 hi+lo, 2 = fp16 hi-only.
// QSCALE: multiply outputs in cols [0, DMODEL) by 0.125 (Q pre-scale).
template <int GELU, int HAS_BIAS, int HAS_RES, int OSPLIT, int HASLO, int QSCALE>
__global__ void __launch_bounds__(256, 2) hgemm_kernel(
    const __half* __restrict__ Ah, const __half* __restrict__ Al,
    const __half* __restrict__ Bh,
    const float* __restrict__ bias, const float* __restrict__ res,
    float* __restrict__ C, __half* __restrict__ Ch,
    __half* __restrict__ Cl, int M, int N, int K) {
    constexpr uint32_t AL_OFF = 8192;
    constexpr uint32_t B_OFF  = HASLO ? 16384 : 8192;
    constexpr uint32_t STG    = HASLO ? 24576 : 16384;
    extern __shared__ __align__(16) char smem[];
    uint32_t uS = smem_u32(smem);

    int tid = threadIdx.x;
    int lane = tid & 31, wid = tid >> 5;
    int wm = wid >> 2, wn = wid & 3;
    int bm = blockIdx.y * 128, bn = blockIdx.x * 128;

    float acc[4][4][4];
    #pragma unroll
    for (int i = 0; i < 4; ++i)
        #pragma unroll
        for (int j = 0; j < 4; ++j)
            #pragma unroll
            for (int k = 0; k < 4; ++k) acc[i][j][k] = 0.0f;

    int q = lane >> 3, rr = lane & 7;
    int a_row = wm * 64 + (q & 1) * 8 + rr;
    int a_cb  = 16 * (q >> 1);
    int b_row = wn * 32 + (q >> 1) * 8 + rr;
    int b_cb  = 16 * (q & 1);

    int lr = tid >> 2, lck = (tid & 3) << 4;
    const int NC = K >> 5;

    auto load_chunk = [&](int c, int s) {
        uint32_t sb = uS + (uint32_t)s * STG;
        int kc = c << 5;
        #pragma unroll
        for (int i = 0; i < 2; ++i) {
            int r = lr + i * 64;
            uint32_t d = sb + SWZ64((uint32_t)(r * 64 + lck));
            CP16(d, Ah + (size_t)(bm + r) * K + kc + (lck >> 1));
            if (HASLO)
                CP16(d + AL_OFF, Al + (size_t)(bm + r) * K + kc + (lck >> 1));
        }
        #pragma unroll
        for (int i = 0; i < 2; ++i) {
            int r = lr + i * 64;
            uint32_t d = sb + B_OFF + SWZ64((uint32_t)(r * 64 + lck));
            CP16(d, Bh + (size_t)(bn + r) * K + kc + (lck >> 1));
        }
        CP_COMMIT();
    };

    load_chunk(0, 0);
    if (NC > 1) load_chunk(1, 1);

    for (int c = 0; c < NC; ++c) {
        if (c + 2 < NC) { load_chunk(c + 2, (c + 2) % 3); CP_WAIT2(); }
        else if (c + 1 < NC) { CP_WAIT1(); }
        else { CP_WAIT0(); }
        __syncthreads();

        uint32_t sb = uS + (uint32_t)(c % 3) * STG;
        #pragma unroll
        for (int ks = 0; ks < 2; ++ks) {
            uint32_t ahf[4][4], alf[4][4];
            #pragma unroll
            for (int mi = 0; mi < 4; ++mi) {
                uint32_t off = sb + SWZ64(
                    (uint32_t)((a_row + mi * 16) * 64 + a_cb + ks * 32));
                LDM_X4(ahf[mi][0], ahf[mi][1], ahf[mi][2], ahf[mi][3], off);
                if (HASLO)
                    LDM_X4(alf[mi][0], alf[mi][1], alf[mi][2], alf[mi][3],
                           off + AL_OFF);
            }
            #pragma unroll
            for (int j2 = 0; j2 < 2; ++j2) {
                uint32_t bhf[2][2];
                uint32_t off = sb + B_OFF + SWZ64(
                    (uint32_t)((b_row + j2 * 16) * 64 + b_cb + ks * 32));
                LDM_X4(bhf[0][0], bhf[0][1], bhf[1][0], bhf[1][1], off);
                #pragma unroll
                for (int mi = 0; mi < 4; ++mi)
                    #pragma unroll
                    for (int nj = 0; nj < 2; ++nj) {
                        int ni = j2 * 2 + nj;
                        MMAH16(acc[mi][ni], ahf[mi], bhf[nj][0], bhf[nj][1]);
                        if (HASLO)
                            MMAH16(acc[mi][ni], alf[mi], bhf[nj][0], bhf[nj][1]);
                    }
            }
        }
        __syncthreads();
    }

    int gid = lane >> 2, tig = lane & 3;
    #pragma unroll
    for (int mi = 0; mi < 4; ++mi) {
        #pragma unroll
        for (int ni = 0; ni < 4; ++ni) {
            int row0 = bm + wm * 64 + mi * 16 + gid;
            int col  = bn + wn * 32 + ni * 8 + tig * 2;
            float c0 = acc[mi][ni][0], c1 = acc[mi][ni][1];
            float c2 = acc[mi][ni][2], c3 = acc[mi][ni][3];
            if (QSCALE) {
                if (col < DMODEL) {
                    c0 *= 0.125f; c1 *= 0.125f; c2 *= 0.125f; c3 *= 0.125f;
                }
            }
            if (HAS_BIAS) {
                float b0 = bias[col], b1v = bias[col + 1];
                c0 += b0; c1 += b1v; c2 += b0; c3 += b1v;
            }
            if (GELU) {
                c0 = gelu_exact(c0); c1 = gelu_exact(c1);
                c2 = gelu_exact(c2); c3 = gelu_exact(c3);
            }
            if (HAS_RES) {
                float2 r0 = *(const float2*)&res[(size_t)row0 * N + col];
                float2 r1 = *(const float2*)&res[(size_t)(row0 + 8) * N + col];
                c0 += r0.x; c1 += r0.y; c2 += r1.x; c3 += r1.y;
            }
            if (OSPLIT == 1) {
                uint32_t h0, l0, h1, l1;
                split2h(c0, c1, h0, l0);
                split2h(c2, c3, h1, l1);
                *(uint32_t*)&Ch[(size_t)row0 * N + col] = h0;
                *(uint32_t*)&Cl[(size_t)row0 * N + col] = l0;
                *(uint32_t*)&Ch[(size_t)(row0 + 8) * N + col] = h1;
                *(uint32_t*)&Cl[(size_t)(row0 + 8) * N + col] = l1;
            } else if (OSPLIT == 2) {
                *(uint32_t*)&Ch[(size_t)row0 * N + col] = pack_h2(c0, c1);
                *(uint32_t*)&Ch[(size_t)(row0 + 8) * N + col] = pack_h2(c2, c3);
            } else {
                float2 o0; o0.x = c0; o0.y = c1;
                float2 o1; o1.x = c2; o1.y = c3;
                *(float2*)&C[(size_t)row0 * N + col] = o0;
                *(float2*)&C[(size_t)(row0 + 8) * N + col] = o1;
            }
        }
    }
}

// ---------------- Tensor-core flash attention -------------------------
// Q pre-scaled by 0.125 (folded into QKV epilogue). Q hi/lo in regs;
// K/V hi-only in smem. S = QhKh + QlKh (2 MMAs); PV = PhVh (1 MMA).
#define AT_V     8192
#define AT_STAGE 16384
#define AT_SMEM  (2 * AT_STAGE)  // 32768

__global__ void __launch_bounds__(128, 3) attn_kernel(
    const __half* __restrict__ QKVh, const __half* __restrict__ QKVl,
    __half* __restrict__ Oh) {
    extern __shared__ __align__(16) char smem[];
    uint32_t uS = smem_u32(smem);

    int qt = 31 - (int)blockIdx.x;   // heavy-first
    int bh = blockIdx.y;
    int b = bh >> 4, h = bh & 15;
    int tid = threadIdx.x, lane = tid & 31, wid = tid >> 5;
    int gid = lane >> 2, tig = lane & 3;
    int q = lane >> 3, rr = lane & 7;

    size_t rowbase = (size_t)b * SEQT;

    auto ld_kv = [&](uint32_t dst, int trow, int cbase) {
        #pragma unroll
        for (int i = 0; i < 4; ++i) {
            int idx = tid + i * 128;
            int r = idx >> 3, c8 = (idx & 7) << 3;
            CP16(dst + SWZ128B((uint32_t)(r * 128 + c8 * 2)),
                 QKVh + (rowbase + trow + r) * (size_t)DM3 + cbase + h * HDIM + c8);
        }
    };

    ld_kv(uS, 0, DMODEL);
    ld_kv(uS + AT_V, 0, 2 * DMODEL);
    CP_COMMIT();

    uint32_t qh[4][4], ql[4][4];
    {
        int row0 = qt * 64 + wid * 16 + gid;
        size_t base0 = (rowbase + row0) * (size_t)DM3 + h * HDIM;
        size_t base8 = base0 + 8 * (size_t)DM3;
        #pragma unroll
        for (int ks = 0; ks < 4; ++ks) {
            int c0 = ks * 16 + 2 * tig;
            qh[ks][0] = *(const uint32_t*)&QKVh[base0 + c0];
            qh[ks][1] = *(const uint32_t*)&QKVh[base8 + c0];
            qh[ks][2] = *(const uint32_t*)&QKVh[base0 + c0 + 8];
            qh[ks][3] = *(const uint32_t*)&QKVh[base8 + c0 + 8];
            ql[ks][0] = *(const uint32_t*)&QKVl[base0 + c0];
            ql[ks][1] = *(const uint32_t*)&QKVl[base8 + c0];
            ql[ks][2] = *(const uint32_t*)&QKVl[base0 + c0 + 8];
            ql[ks][3] = *(const uint32_t*)&QKVl[base8 + c0 + 8];
        }
    }

    float oacc[8][4];
    #pragma unroll
    for (int i = 0; i < 8; ++i)
        #pragma unroll
        for (int j = 0; j < 4; ++j) oacc[i][j] = 0.0f;
    float m0 = -1e30f, m1 = -1e30f, l0 = 0.0f, l1 = 0.0f;

    int b_rsel = (q >> 1) * 8 + rr;
    int b_csel = (q & 1) * 8;
    int v_rsel = (q & 1) * 8 + rr;
    int v_csel = (q >> 1) * 8;

    for (int kt = 0; kt <= qt; ++kt) {
        uint32_t st = uS + (uint32_t)(kt & 1) * AT_STAGE;
        if (kt < qt) {
            uint32_t s2 = uS + (uint32_t)((kt + 1) & 1) * AT_STAGE;
            ld_kv(s2, (kt + 1) * 64, DMODEL);
            ld_kv(s2 + AT_V, (kt + 1) * 64, 2 * DMODEL);
            CP_COMMIT();
            CP_WAIT1();
        } else {
            CP_WAIT0();
        }
        __syncthreads();

        float sc[8][4];
        #pragma unroll
        for (int i = 0; i < 8; ++i)
            #pragma unroll
            for (int j = 0; j < 4; ++j) sc[i][j] = 0.0f;

        #pragma unroll
        for (int ks = 0; ks < 4; ++ks) {
            #pragma unroll
            for (int j2 = 0; j2 < 4; ++j2) {
                uint32_t kh0, kh1, kh2, kh3;
                uint32_t boff = st + SWZ128B(
                    (uint32_t)((j2 * 16 + b_rsel) * 128 + (b_csel + ks * 16) * 2));
                LDM_X4(kh0, kh1, kh2, kh3, boff);
                MMAH16(sc[2 * j2],     qh[ks], kh0, kh1);
                MMAH16(sc[2 * j2],     ql[ks], kh0, kh1);
                MMAH16(sc[2 * j2 + 1], qh[ks], kh2, kh3);
                MMAH16(sc[2 * j2 + 1], ql[ks], kh2, kh3);
            }
        }

        // causal mask (Q already pre-scaled; logits are final)
        if (kt == qt) {
            int r0 = wid * 16 + gid, r1 = r0 + 8;
            #pragma unroll
            for (int ni = 0; ni < 8; ++ni) {
                int c0 = ni * 8 + tig * 2, c1 = c0 + 1;
                if (c0 > r0) sc[ni][0] = -1e30f;
                if (c1 > r0) sc[ni][1] = -1e30f;
                if (c0 > r1) sc[ni][2] = -1e30f;
                if (c1 > r1) sc[ni][3] = -1e30f;
            }
        }

        float t0 = -1e30f, t1 = -1e30f;
        #pragma unroll
        for (int ni = 0; ni < 8; ++ni) {
            t0 = fmaxf(t0, fmaxf(sc[ni][0], sc[ni][1]));
            t1 = fmaxf(t1, fmaxf(sc[ni][2], sc[ni][3]));
        }
        t0 = fmaxf(t0, __shfl_xor_sync(0xffffffffu, t0, 1));
        t0 = fmaxf(t0, __shfl_xor_sync(0xffffffffu, t0, 2));
        t1 = fmaxf(t1, __shfl_xor_sync(0xffffffffu, t1, 1));
        t1 = fmaxf(t1, __shfl_xor_sync(0xffffffffu, t1, 2));
        float mn0 = fmaxf(m0, t0), mn1 = fmaxf(m1, t1);
        float al0 = __expf(m0 - mn0), al1 = __expf(m1 - mn1);
        m0 = mn0; m1 = mn1;

        float sum0 = 0.0f, sum1 = 0.0f;
        uint32_t pah[4][4];
        #pragma unroll
        for (int kp = 0; kp < 4; ++kp) {
            float p00 = __expf(sc[2 * kp][0] - mn0);
            float p01 = __expf(sc[2 * kp][1] - mn0);
            float p02 = __expf(sc[2 * kp][2] - mn1);
            float p03 = __expf(sc[2 * kp][3] - mn1);
            float p10 = __expf(sc[2 * kp + 1][0] - mn0);
            float p11 = __expf(sc[2 * kp + 1][1] - mn0);
            float p12 = __expf(sc[2 * kp + 1][2] - mn1);
            float p13 = __expf(sc[2 * kp + 1][3] - mn1);
            sum0 += p00 + p01 + p10 + p11;
            sum1 += p02 + p03 + p12 + p13;
            pah[kp][0] = pack_h2(p00, p01);
            pah[kp][1] = pack_h2(p02, p03);
            pah[kp][2] = pack_h2(p10, p11);
            pah[kp][3] = pack_h2(p12, p13);
        }
        sum0 += __shfl_xor_sync(0xffffffffu, sum0, 1);
        sum0 += __shfl_xor_sync(0xffffffffu, sum0, 2);
        sum1 += __shfl_xor_sync(0xffffffffu, sum1, 1);
        sum1 += __shfl_xor_sync(0xffffffffu, sum1, 2);
        l0 = l0 * al0 + sum0;
        l1 = l1 * al1 + sum1;
        #pragma unroll
        for (int ni = 0; ni < 8; ++ni) {
            oacc[ni][0] *= al0; oacc[ni][1] *= al0;
            oacc[ni][2] *= al1; oacc[ni][3] *= al1;
        }

        #pragma unroll
        for (int ks = 0; ks < 4; ++ks) {
            #pragma unroll
            for (int j2 = 0; j2 < 4; ++j2) {
                uint32_t vh0, vh1, vh2, vh3;
                uint32_t voff = st + AT_V + SWZ128B(
                    (uint32_t)((ks * 16 + v_rsel) * 128 + (v_csel + j2 * 16) * 2));
                LDM_X4T(vh0, vh1, vh2, vh3, voff);
                MMAH16(oacc[2 * j2],     pah[ks], vh0, vh1);
                MMAH16(oacc[2 * j2 + 1], pah[ks], vh2, vh3);
            }
        }
        __syncthreads();
    }

    float inv0 = 1.0f / l0, inv1 = 1.0f / l1;
    int grow = qt * 64 + wid * 16 + gid;
    #pragma unroll
    for (int ni = 0; ni < 8; ++ni) {
        size_t i0 = (rowbase + grow) * (size_t)DMODEL + h * HDIM + ni * 8 + tig * 2;
        size_t i1 = i0 + 8 * (size_t)DMODEL;
        *(uint32_t*)&Oh[i0] = pack_h2(oacc[ni][0] * inv0, oacc[ni][1] * inv0);
        *(uint32_t*)&Oh[i1] = pack_h2(oacc[ni][2] * inv1, oacc[ni][3] * inv1);
    }
}

// ---------------- launch -------------------------------------------
static void* sym_addr(const void* sym) {
    void* p = nullptr;
    cudaGetSymbolAddress(&p, sym);
    return p;
}

extern "C" void kernel_launch(void* const* d_in, const int* in_sizes, int n_in,
                              void* d_out, int out_size) {
    const float* x     = (const float*)d_in[0];
    const float* ln1_g = (const float*)d_in[1];
    const float* ln1_b = (const float*)d_in[2];
    const float* Wq    = (const float*)d_in[3];
    const float* Wk    = (const float*)d_in[4];
    const float* Wv    = (const float*)d_in[5];
    const float* Wo    = (const float*)d_in[6];
    const float* ln2_g = (const float*)d_in[7];
    const float* ln2_b = (const float*)d_in[8];
    const float* W1    = (const float*)d_in[9];
    const float* b1    = (const float*)d_in[10];
    const float* W2    = (const float*)d_in[11];
    const float* b2    = (const float*)d_in[12];
    float* out = (float*)d_out;

    float* x2 = (float*)sym_addr(g_x2);
    __half* lnh  = (__half*)sym_addr(g_lnh);
    __half* lnl  = (__half*)sym_addr(g_lnl);
    __half* qkvh = (__half*)sym_addr(g_qkvh);
    __half* qkvl = (__half*)sym_addr(g_qkvl);
    __half* ctxh = (__half*)sym_addr(g_ctxh);
    __half* ffh  = (__half*)sym_addr(g_ffh);

    __half* Bqkv = (__half*)sym_addr(g_Bqkv);
    __half* Bo   = (__half*)sym_addr(g_Bo);
    __half* B1   = (__half*)sym_addr(g_B1);
    __half* B2   = (__half*)sym_addr(g_B2);

    cudaFuncSetAttribute(hgemm_kernel<0, 0, 0, 1, 1, 1>,
                         cudaFuncAttributeMaxDynamicSharedMemorySize, 3 * 24576);
    cudaFuncSetAttribute(hgemm_kernel<1, 1, 0, 2, 1, 0>,
                         cudaFuncAttributeMaxDynamicSharedMemorySize, 3 * 24576);
    cudaFuncSetAttribute(hgemm_kernel<0, 0, 1, 0, 0, 0>,
                         cudaFuncAttributeMaxDynamicSharedMemorySize, 3 * 16384);
    cudaFuncSetAttribute(hgemm_kernel<0, 1, 1, 0, 0, 0>,
                         cudaFuncAttributeMaxDynamicSharedMemorySize, 3 * 16384);
    cudaFuncSetAttribute(attn_kernel,
                         cudaFuncAttributeMaxDynamicSharedMemorySize, AT_SMEM);

    dim3 blk128(128), blk256(256);
    dim3 gqkv(DM3 / 128, MROWS / 128);         // (24, 32)
    dim3 g1k(DMODEL / 128, MROWS / 128);       // (8, 32)
    dim3 g2k(2 * DMODEL / 128, MROWS / 128);   // (16, 32)

    // 0: weight prep (fp16 hi-only transposed weights)
    wsplit_all_kernel<<<8192, blk256>>>(Wq, Wk, Wv, Bqkv, Wo, Bo,
                                        W1, B1, W2, B2);
    // 1: LN1 -> fp16 hi/lo
    ln_kernel<<<MROWS, blk256>>>(x, ln1_g, ln1_b, lnh, lnl);
    // 2: merged QKV projection (2-product, Q cols pre-scaled) -> fp16 hi/lo
    hgemm_kernel<0, 0, 0, 1, 1, 1><<<gqkv, blk256, 3 * 24576>>>(
        lnh, lnl, Bqkv, nullptr, nullptr, nullptr, qkvh, qkvl,
        MROWS, DM3, DMODEL);
    // 3: attention (S 2-product, PV 1-product) -> ctx fp16 hi-only
    attn_kernel<<<dim3(32, 32), blk128, AT_SMEM>>>(qkvh, qkvl, ctxh);
    // 4: output projection (1-product) + residual(x) -> x2 fp32
    hgemm_kernel<0, 0, 1, 0, 0, 0><<<g1k, blk256, 3 * 16384>>>(
        ctxh, nullptr, Bo, nullptr, x, x2, nullptr, nullptr,
        MROWS, DMODEL, DMODEL);
    // 5: LN2 -> fp16 hi/lo
    ln_kernel<<<MROWS, blk256>>>(x2, ln2_g, ln2_b, lnh, lnl);
    // 6: FFN up (2-product) + bias + GELU -> ff fp16 hi-only
    hgemm_kernel<1, 1, 0, 2, 1, 0><<<g2k, blk256, 3 * 24576>>>(
        lnh, lnl, B1, b1, nullptr, nullptr, ffh, nullptr,
        MROWS, 2 * DMODEL, DMODEL);
    // 7: FFN down (1-product) + bias + residual(x2) -> out fp32
    hgemm_kernel<0, 1, 1, 0, 0, 0><<<g1k, blk256, 3 * 16384>>>(
        ffh, nullptr, B2, b2, x2, out, nullptr, nullptr,
        MROWS, DMODEL, 2 * DMODEL);
}